// round 1
// baseline (speedup 1.0000x reference)
#include <cuda_runtime.h>
#include <math.h>

// Problem constants
#define BATCH   16384
#define OBS     568
#define HDIM    256
#define SELFD   36
#define OTHD    28
#define NOTH    19          // (568-36)/28
#define MROWS   (BATCH*NOTH)

// ---------------------------------------------------------------------------
// Scratch (device globals; allocation is forbidden)
// ---------------------------------------------------------------------------
__device__ float g_mu   [BATCH*HDIM];
__device__ float g_lv   [BATCH*HDIM];
__device__ float g_z    [BATCH*HDIM];
__device__ float g_q    [BATCH*HDIM];
__device__ float g_h    [BATCH*HDIM];
__device__ float g_self [BATCH*HDIM];
__device__ float g_sev  [BATCH*HDIM];   // self_em @ W_v[256:] + b_v
__device__ float g_spa  [BATCH*HDIM];   // self_em @ W_a[256:] + b_a
__device__ float g_other[MROWS*HDIM];
__device__ float g_k    [MROWS*HDIM];
__device__ float g_v    [MROWS*HDIM];

// ---------------------------------------------------------------------------
// Generic tiled SGEMM: C[M,N] = epi(A[M,K] @ W[K,N] (+ bias / + extra))
// AMAP: 0 = A row base = row*lda;  1 = agents view of x
// EPI : 0 = +bias; 1 = relu(+bias); 2 = relu(+extra[(row/rowdiv)*N + col])
// BM=BN=64, BK=16, 256 threads, 4x4 microtile.
// ---------------------------------------------------------------------------
template<int AMAP, int EPI>
__global__ void __launch_bounds__(256)
sgemm_kernel(const float* __restrict__ A, int lda,
             const float* __restrict__ W,
             const float* __restrict__ bias,
             const float* __restrict__ extra, int rowdiv,
             float* __restrict__ C,
             int M, int N, int K)
{
    __shared__ __align__(16) float As[16][64];
    __shared__ __align__(16) float Bs[16][64];

    const int tid     = threadIdx.x;
    const int rowBase = blockIdx.y * 64;
    const int colBase = blockIdx.x * 64;

    // A-tile load mapping: 64 rows x 16 k, 4 consecutive k per thread
    const int a_m  = tid >> 2;         // 0..63
    const int a_k0 = (tid & 3) * 4;    // 0,4,8,12
    // B-tile load mapping: 16 k x 64 n, float4 per thread
    const int b_k  = tid >> 4;         // 0..15
    const int b_n0 = (tid & 15) * 4;

    const int ty = tid >> 4;           // 0..15  (row group)
    const int tx = tid & 15;           // 0..15  (col group)

    // Per-row A base offset
    const int a_row = rowBase + a_m;
    const bool a_ok = (a_row < M);
    long a_base;
    if (AMAP == 0) {
        a_base = (long)a_row * lda;
    } else {
        const int bb = a_row / NOTH;
        const int nn = a_row - bb * NOTH;
        a_base = (long)bb * OBS + SELFD + nn * OTHD;
    }

    float acc[4][4];
#pragma unroll
    for (int i = 0; i < 4; i++)
#pragma unroll
        for (int j = 0; j < 4; j++) acc[i][j] = 0.f;

    for (int kt = 0; kt < K; kt += 16) {
        // load A tile
#pragma unroll
        for (int i = 0; i < 4; i++) {
            const int kg = kt + a_k0 + i;
            As[a_k0 + i][a_m] = (a_ok && kg < K) ? A[a_base + kg] : 0.f;
        }
        // load B tile (vectorized; N==256 and colBase/b_n0 are 4-aligned)
        const int kgb = kt + b_k;
        float4 bv = make_float4(0.f, 0.f, 0.f, 0.f);
        if (kgb < K)
            bv = *reinterpret_cast<const float4*>(&W[(long)kgb * N + colBase + b_n0]);
        *reinterpret_cast<float4*>(&Bs[b_k][b_n0]) = bv;

        __syncthreads();

#pragma unroll
        for (int kk = 0; kk < 16; kk++) {
            const float4 av = *reinterpret_cast<const float4*>(&As[kk][ty * 4]);
            const float4 bw = *reinterpret_cast<const float4*>(&Bs[kk][tx * 4]);
            const float ar[4] = {av.x, av.y, av.z, av.w};
            const float br[4] = {bw.x, bw.y, bw.z, bw.w};
#pragma unroll
            for (int i = 0; i < 4; i++)
#pragma unroll
                for (int j = 0; j < 4; j++)
                    acc[i][j] = fmaf(ar[i], br[j], acc[i][j]);
        }
        __syncthreads();
    }

    // epilogue
#pragma unroll
    for (int i = 0; i < 4; i++) {
        const int row = rowBase + ty * 4 + i;
        if (row >= M) continue;
#pragma unroll
        for (int j = 0; j < 4; j++) {
            const int col = colBase + tx * 4 + j;
            float val = acc[i][j];
            if (EPI == 2) {
                val += extra[(long)(row / rowdiv) * N + col];
            } else {
                val += bias[col];
            }
            if (EPI >= 1) val = fmaxf(val, 0.f);
            C[(long)row * N + col] = val;
        }
    }
}

// ---------------------------------------------------------------------------
// z = eps * exp(0.5*log_var) + mu
// ---------------------------------------------------------------------------
__global__ void z_kernel(const float* __restrict__ eps,
                         const float* __restrict__ mu,
                         const float* __restrict__ lv,
                         float* __restrict__ z, int n)
{
    int i = blockIdx.x * blockDim.x + threadIdx.x;
    if (i < n) z[i] = fmaf(eps[i], expf(0.5f * lv[i]), mu[i]);
}

// ---------------------------------------------------------------------------
// Attention: scores = q.k/16 -> softmax(19) -> h = att @ v ; att -> out
// One block (256 thr) per batch row.
// ---------------------------------------------------------------------------
__global__ void __launch_bounds__(256)
att_kernel(const float* __restrict__ q,
           const float* __restrict__ k,
           const float* __restrict__ v,
           float* __restrict__ h,
           float* __restrict__ att_out)
{
    const int b   = blockIdx.x;
    const int tid = threadIdx.x;
    const int wid = tid >> 5;
    const int lane = tid & 31;

    __shared__ float qs[HDIM];
    __shared__ float sc[32];

    qs[tid] = q[(long)b * HDIM + tid];
    __syncthreads();

    // scores: warp per n
    for (int n = wid; n < NOTH; n += 8) {
        const float* kp = k + ((long)b * NOTH + n) * HDIM;
        float p = 0.f;
#pragma unroll
        for (int j = 0; j < 8; j++) {
            const int c = lane + 32 * j;
            p = fmaf(qs[c], kp[c], p);
        }
#pragma unroll
        for (int off = 16; off > 0; off >>= 1)
            p += __shfl_xor_sync(0xffffffffu, p, off);
        if (lane == 0) sc[n] = p * 0.0625f;   // 1/sqrt(256)
    }
    __syncthreads();

    // softmax over 19 (single warp)
    if (wid == 0) {
        float s = (lane < NOTH) ? sc[lane] : -INFINITY;
        float m = s;
#pragma unroll
        for (int off = 16; off > 0; off >>= 1)
            m = fmaxf(m, __shfl_xor_sync(0xffffffffu, m, off));
        float e = (lane < NOTH) ? expf(s - m) : 0.f;
        float sum = e;
#pragma unroll
        for (int off = 16; off > 0; off >>= 1)
            sum += __shfl_xor_sync(0xffffffffu, sum, off);
        const float a = e / sum;
        if (lane < NOTH) {
            sc[lane] = a;
            att_out[(long)b * NOTH + lane] = a;
        }
    }
    __syncthreads();

    // h[b, tid] = sum_n att[n] * v[b, n, tid]
    float acc = 0.f;
    const float* vp = v + (long)b * NOTH * HDIM + tid;
#pragma unroll
    for (int n = 0; n < NOTH; n++)
        acc = fmaf(sc[n], vp[(long)n * HDIM], acc);
    h[(long)b * HDIM + tid] = acc;
}

// ---------------------------------------------------------------------------
// Launch
// ---------------------------------------------------------------------------
extern "C" void kernel_launch(void* const* d_in, const int* in_sizes, int n_in,
                              void* d_out, int out_size)
{
    const float* x      = (const float*)d_in[0];
    const float* eps    = (const float*)d_in[1];
    const float* W_mu   = (const float*)d_in[2];
    const float* b_mu   = (const float*)d_in[3];
    const float* W_var  = (const float*)d_in[4];
    const float* b_var  = (const float*)d_in[5];
    const float* W_self = (const float*)d_in[6];
    const float* b_self = (const float*)d_in[7];
    const float* W_oth  = (const float*)d_in[8];
    const float* b_oth  = (const float*)d_in[9];
    const float* W_q    = (const float*)d_in[10];
    const float* b_q    = (const float*)d_in[11];
    const float* W_k    = (const float*)d_in[12];
    const float* b_k    = (const float*)d_in[13];
    const float* W_v    = (const float*)d_in[14];
    const float* b_v    = (const float*)d_in[15];
    const float* W_a    = (const float*)d_in[16];
    const float* b_a    = (const float*)d_in[17];

    float* out_main = (float*)d_out;                      // [B,256]
    float* out_att  = (float*)d_out + (long)BATCH * HDIM; // [B,19]

    float *mu, *lv, *z, *q, *h, *self_em, *sev, *spa, *oth, *kb, *vb;
    cudaGetSymbolAddress((void**)&mu,      g_mu);
    cudaGetSymbolAddress((void**)&lv,      g_lv);
    cudaGetSymbolAddress((void**)&z,       g_z);
    cudaGetSymbolAddress((void**)&q,       g_q);
    cudaGetSymbolAddress((void**)&h,       g_h);
    cudaGetSymbolAddress((void**)&self_em, g_self);
    cudaGetSymbolAddress((void**)&sev,     g_sev);
    cudaGetSymbolAddress((void**)&spa,     g_spa);
    cudaGetSymbolAddress((void**)&oth,     g_other);
    cudaGetSymbolAddress((void**)&kb,      g_k);
    cudaGetSymbolAddress((void**)&vb,      g_v);

    const dim3 blk(256);
    const dim3 gB (HDIM / 64, BATCH / 64);   // M = B
    const dim3 gM (HDIM / 64, MROWS / 64);   // M = B*19

    // mu / log_var
    sgemm_kernel<0,0><<<gB, blk>>>(x, OBS, W_mu,  b_mu,  nullptr, 1, mu, BATCH, HDIM, OBS);
    sgemm_kernel<0,0><<<gB, blk>>>(x, OBS, W_var, b_var, nullptr, 1, lv, BATCH, HDIM, OBS);
    {
        const int n = BATCH * HDIM;
        z_kernel<<<(n + 255) / 256, 256>>>(eps, mu, lv, z, n);
    }
    // self_em = relu(x[:, :36] @ W_self + b)
    sgemm_kernel<0,1><<<gB, blk>>>(x, OBS, W_self, b_self, nullptr, 1, self_em, BATCH, HDIM, SELFD);
    // other_ems = relu(agents @ W_other + b)
    sgemm_kernel<1,1><<<gM, blk>>>(x, 0, W_oth, b_oth, nullptr, 1, oth, MROWS, HDIM, OTHD);
    // q = relu(z @ W_q + b)
    sgemm_kernel<0,1><<<gB, blk>>>(z, HDIM, W_q, b_q, nullptr, 1, q, BATCH, HDIM, HDIM);
    // k = relu(other_ems @ W_k + b)
    sgemm_kernel<0,1><<<gM, blk>>>(oth, HDIM, W_k, b_k, nullptr, 1, kb, MROWS, HDIM, HDIM);
    // sev = self_em @ W_v[256:] + b_v
    sgemm_kernel<0,0><<<gB, blk>>>(self_em, HDIM, W_v + HDIM * HDIM, b_v, nullptr, 1, sev, BATCH, HDIM, HDIM);
    // v = relu(other_ems @ W_v[:256] + sev[b])
    sgemm_kernel<0,2><<<gM, blk>>>(oth, HDIM, W_v, nullptr, sev, NOTH, vb, MROWS, HDIM, HDIM);
    // attention: scores/softmax/h ; writes att to output
    att_kernel<<<BATCH, 256>>>(q, kb, vb, h, out_att);
    // spa = self_em @ W_a[256:] + b_a
    sgemm_kernel<0,0><<<gB, blk>>>(self_em, HDIM, W_a + HDIM * HDIM, b_a, nullptr, 1, spa, BATCH, HDIM, HDIM);
    // out = relu(h @ W_a[:256] + spa[b])
    sgemm_kernel<0,2><<<gB, blk>>>(h, HDIM, W_a, nullptr, spa, 1, out_main, BATCH, HDIM, HDIM);
}

// round 5
// speedup vs baseline: 2.1502x; 2.1502x over previous
#include <cuda_runtime.h>
#include <math.h>

// Problem constants
#define BATCH   16384
#define OBS     568
#define HDIM    256
#define SELFD   36
#define OTHD    28
#define NOTH    19          // (568-36)/28
#define MROWS   (BATCH*NOTH)

// ---------------------------------------------------------------------------
// Scratch (device globals; allocation is forbidden)
// ---------------------------------------------------------------------------
__device__ float g_mu   [BATCH*HDIM];
__device__ float g_lv   [BATCH*HDIM];
__device__ float g_z    [BATCH*HDIM];
__device__ float g_q    [BATCH*HDIM];
__device__ float g_h    [BATCH*HDIM];
__device__ float g_self [BATCH*HDIM];
__device__ float g_sev  [BATCH*HDIM];   // self_em @ W_v[256:] + b_v
__device__ float g_spa  [BATCH*HDIM];   // self_em @ W_a[256:] + b_a
__device__ float g_other[MROWS*HDIM];
__device__ float g_k    [MROWS*HDIM];
__device__ float g_v    [MROWS*HDIM];

// ---------------------------------------------------------------------------
// fp32 -> tf32 (round to nearest)
// ---------------------------------------------------------------------------
__device__ __forceinline__ unsigned f2tf(float f) {
    unsigned u;
    asm("cvt.rna.tf32.f32 %0, %1;" : "=r"(u) : "f"(f));
    return u;
}

// ---------------------------------------------------------------------------
// TF32 tensor-core GEMM: C[M,N] = epi(A[M,K] @ W[K,N])
// BM=128, BN=64, BK=32, 256 threads (8 warps, 4x2), warp tile 32x32
// via mma.sync.m16n8k8.tf32, fp32 accumulate. Double-buffered smem.
// AMAP: 0 = A row base = row*lda;  1 = agents view of x
// EPI : 0 = +bias; 1 = relu(+bias); 2 = relu(+extra[(row/rowdiv)*N + col])
// Requires: M % 128 == 0, N % 64 == 0 (true for all call sites).
// ---------------------------------------------------------------------------
template<int AMAP, int EPI>
__global__ void __launch_bounds__(256, 2)
tgemm(const float* __restrict__ A, int lda,
      const float* __restrict__ W,
      const float* __restrict__ bias,
      const float* __restrict__ extra, int rowdiv,
      float* __restrict__ C, int M, int N, int K)
{
    // As: element (k, m) at [k>>2][m][k&3]  -> STS.128 per global float4,
    //     conflict-free A-fragment LDS (bank = g*4 + t).
    // Bs: element (k, n) at [k][n ^ ((k&3)<<3)] -> conflict-free B-fragment LDS.
    __shared__ unsigned As[2][8][128][4];
    __shared__ unsigned Bs[2][32][64];

    const int tid  = threadIdx.x;
    const int lane = tid & 31;
    const int wid  = tid >> 5;
    const int wm   = wid >> 1;   // 0..3
    const int wn   = wid & 1;    // 0..1
    const int g    = lane >> 2;  // 0..7
    const int t    = lane & 3;   // 0..3

    const long rowBase = (long)blockIdx.y * 128;
    const int  colBase = blockIdx.x * 64;

    // A global load mapping: 4 sub-loads of float4 (m, k0..k0+3)
    int am[4], ak0[4]; long abase[4];
#pragma unroll
    for (int j = 0; j < 4; j++) {
        int idx = tid + j * 256;          // 0..1023
        am[j]  = idx >> 3;                // 0..127
        ak0[j] = (idx & 7) << 2;          // 0,4,...,28
        long row = rowBase + am[j];
        if (AMAP == 0) {
            abase[j] = row * lda;
        } else {
            int bb = (int)(row / NOTH);
            int nn = (int)(row - (long)bb * NOTH);
            abase[j] = (long)bb * OBS + SELFD + nn * OTHD;
        }
    }
    // B global load mapping: 2 sub-loads of float4 (k, n0..n0+3)
    int bn0[2], bk[2];
#pragma unroll
    for (int j = 0; j < 2; j++) {
        int idx = tid + j * 256;          // 0..511
        bn0[j] = (idx & 15) << 2;         // 0..60
        bk[j]  = idx >> 4;                // 0..31
    }

    float acc[2][4][4];
#pragma unroll
    for (int mi = 0; mi < 2; mi++)
#pragma unroll
        for (int ni = 0; ni < 4; ni++)
#pragma unroll
            for (int c = 0; c < 4; c++) acc[mi][ni][c] = 0.f;

    const int kTiles = (K + 31) >> 5;

    float4 aR[4], bR[2];

    // ---- tile load (global -> regs) ----
    auto loadTile = [&](int tileIdx) {
        const int kt = tileIdx << 5;
        if (kt + 32 <= K) {
#pragma unroll
            for (int j = 0; j < 4; j++)
                aR[j] = *reinterpret_cast<const float4*>(&A[abase[j] + kt + ak0[j]]);
#pragma unroll
            for (int j = 0; j < 2; j++)
                bR[j] = *reinterpret_cast<const float4*>(&W[(long)(kt + bk[j]) * N + colBase + bn0[j]]);
        } else {
#pragma unroll
            for (int j = 0; j < 4; j++) {
                float v[4];
#pragma unroll
                for (int i = 0; i < 4; i++) {
                    int kg = kt + ak0[j] + i;
                    v[i] = (kg < K) ? A[abase[j] + kg] : 0.f;
                }
                aR[j] = make_float4(v[0], v[1], v[2], v[3]);
            }
#pragma unroll
            for (int j = 0; j < 2; j++) {
                int kg = kt + bk[j];
                bR[j] = (kg < K)
                    ? *reinterpret_cast<const float4*>(&W[(long)kg * N + colBase + bn0[j]])
                    : make_float4(0.f, 0.f, 0.f, 0.f);
            }
        }
    };
    // ---- tile store (regs -> smem, with tf32 conversion) ----
    auto stsTile = [&](int buf) {
#pragma unroll
        for (int j = 0; j < 4; j++) {
            uint4 u = make_uint4(f2tf(aR[j].x), f2tf(aR[j].y), f2tf(aR[j].z), f2tf(aR[j].w));
            *reinterpret_cast<uint4*>(&As[buf][ak0[j] >> 2][am[j]][0]) = u;
        }
#pragma unroll
        for (int j = 0; j < 2; j++) {
            uint4 u = make_uint4(f2tf(bR[j].x), f2tf(bR[j].y), f2tf(bR[j].z), f2tf(bR[j].w));
            int k = bk[j];
            *reinterpret_cast<uint4*>(&Bs[buf][k][bn0[j] ^ ((k & 3) << 3)]) = u;
        }
    };

    loadTile(0);
    stsTile(0);
    __syncthreads();

    for (int tile = 0; tile < kTiles; tile++) {
        const int cur = tile & 1;
        const bool havenext = (tile + 1 < kTiles);
        if (havenext) loadTile(tile + 1);

#pragma unroll
        for (int ks = 0; ks < 4; ks++) {
            const int kk = ks * 8;
            unsigned a[2][4], b[4][2];
#pragma unroll
            for (int mi = 0; mi < 2; mi++) {
                const int m0 = wm * 32 + mi * 16 + g;
                a[mi][0] = As[cur][(kk >> 2)    ][m0    ][t];
                a[mi][1] = As[cur][(kk >> 2)    ][m0 + 8][t];
                a[mi][2] = As[cur][(kk >> 2) + 1][m0    ][t];
                a[mi][3] = As[cur][(kk >> 2) + 1][m0 + 8][t];
            }
#pragma unroll
            for (int ni = 0; ni < 4; ni++) {
                const int nsw = (wn * 32 + ni * 8 + g) ^ (t << 3);
                b[ni][0] = Bs[cur][kk + t    ][nsw];
                b[ni][1] = Bs[cur][kk + t + 4][nsw];
            }
#pragma unroll
            for (int mi = 0; mi < 2; mi++)
#pragma unroll
                for (int ni = 0; ni < 4; ni++) {
                    asm volatile(
                        "mma.sync.aligned.m16n8k8.row.col.f32.tf32.tf32.f32 "
                        "{%0,%1,%2,%3},{%4,%5,%6,%7},{%8,%9},{%0,%1,%2,%3};"
                        : "+f"(acc[mi][ni][0]), "+f"(acc[mi][ni][1]),
                          "+f"(acc[mi][ni][2]), "+f"(acc[mi][ni][3])
                        : "r"(a[mi][0]), "r"(a[mi][1]), "r"(a[mi][2]), "r"(a[mi][3]),
                          "r"(b[ni][0]), "r"(b[ni][1]));
                }
        }

        if (havenext) stsTile(1 - cur);
        __syncthreads();
    }

    // ---- epilogue ----
#pragma unroll
    for (int mi = 0; mi < 2; mi++) {
#pragma unroll
        for (int d = 0; d < 2; d++) {
            const long row = rowBase + wm * 32 + mi * 16 + g + d * 8;
            const float* ex = (EPI == 2) ? &extra[(row / rowdiv) * N] : nullptr;
#pragma unroll
            for (int ni = 0; ni < 4; ni++) {
                const int col = colBase + wn * 32 + ni * 8 + 2 * t;
                float v0 = acc[mi][ni][2 * d];
                float v1 = acc[mi][ni][2 * d + 1];
                if (EPI == 2) {
                    v0 += ex[col];
                    v1 += ex[col + 1];
                } else {
                    v0 += bias[col];
                    v1 += bias[col + 1];
                }
                if (EPI >= 1) { v0 = fmaxf(v0, 0.f); v1 = fmaxf(v1, 0.f); }
                *reinterpret_cast<float2*>(&C[row * N + col]) = make_float2(v0, v1);
            }
        }
    }
}

// ---------------------------------------------------------------------------
// z = eps * exp(0.5*log_var) + mu
// ---------------------------------------------------------------------------
__global__ void z_kernel(const float* __restrict__ eps,
                         const float* __restrict__ mu,
                         const float* __restrict__ lv,
                         float* __restrict__ z, int n)
{
    int i = blockIdx.x * blockDim.x + threadIdx.x;
    if (i < n) z[i] = fmaf(eps[i], expf(0.5f * lv[i]), mu[i]);
}

// ---------------------------------------------------------------------------
// Attention: scores = q.k/16 -> softmax(19) -> h = att @ v ; att -> out
// One block (256 thr) per batch row.
// ---------------------------------------------------------------------------
__global__ void __launch_bounds__(256)
att_kernel(const float* __restrict__ q,
           const float* __restrict__ k,
           const float* __restrict__ v,
           float* __restrict__ h,
           float* __restrict__ att_out)
{
    const int b   = blockIdx.x;
    const int tid = threadIdx.x;
    const int wid = tid >> 5;
    const int lane = tid & 31;

    __shared__ float qs[HDIM];
    __shared__ float sc[32];

    qs[tid] = q[(long)b * HDIM + tid];
    __syncthreads();

    for (int n = wid; n < NOTH; n += 8) {
        const float* kp = k + ((long)b * NOTH + n) * HDIM;
        float p = 0.f;
#pragma unroll
        for (int j = 0; j < 8; j++) {
            const int c = lane + 32 * j;
            p = fmaf(qs[c], kp[c], p);
        }
#pragma unroll
        for (int off = 16; off > 0; off >>= 1)
            p += __shfl_xor_sync(0xffffffffu, p, off);
        if (lane == 0) sc[n] = p * 0.0625f;   // 1/sqrt(256)
    }
    __syncthreads();

    if (wid == 0) {
        float s = (lane < NOTH) ? sc[lane] : -INFINITY;
        float m = s;
#pragma unroll
        for (int off = 16; off > 0; off >>= 1)
            m = fmaxf(m, __shfl_xor_sync(0xffffffffu, m, off));
        float e = (lane < NOTH) ? expf(s - m) : 0.f;
        float sum = e;
#pragma unroll
        for (int off = 16; off > 0; off >>= 1)
            sum += __shfl_xor_sync(0xffffffffu, sum, off);
        const float a = e / sum;
        if (lane < NOTH) {
            sc[lane] = a;
            att_out[(long)b * NOTH + lane] = a;
        }
    }
    __syncthreads();

    float acc = 0.f;
    const float* vp = v + (long)b * NOTH * HDIM + tid;
#pragma unroll
    for (int n = 0; n < NOTH; n++)
        acc = fmaf(sc[n], vp[(long)n * HDIM], acc);
    h[(long)b * HDIM + tid] = acc;
}

// ---------------------------------------------------------------------------
// Launch
// ---------------------------------------------------------------------------
extern "C" void kernel_launch(void* const* d_in, const int* in_sizes, int n_in,
                              void* d_out, int out_size)
{
    const float* x      = (const float*)d_in[0];
    const float* eps    = (const float*)d_in[1];
    const float* W_mu   = (const float*)d_in[2];
    const float* b_mu   = (const float*)d_in[3];
    const float* W_var  = (const float*)d_in[4];
    const float* b_var  = (const float*)d_in[5];
    const float* W_self = (const float*)d_in[6];
    const float* b_self = (const float*)d_in[7];
    const float* W_oth  = (const float*)d_in[8];
    const float* b_oth  = (const float*)d_in[9];
    const float* W_q    = (const float*)d_in[10];
    const float* b_q    = (const float*)d_in[11];
    const float* W_k    = (const float*)d_in[12];
    const float* b_k    = (const float*)d_in[13];
    const float* W_v    = (const float*)d_in[14];
    const float* b_v    = (const float*)d_in[15];
    const float* W_a    = (const float*)d_in[16];
    const float* b_a    = (const float*)d_in[17];

    float* out_main = (float*)d_out;                      // [B,256]
    float* out_att  = (float*)d_out + (long)BATCH * HDIM; // [B,19]

    float *mu, *lv, *z, *q, *h, *self_em, *sev, *spa, *oth, *kb, *vb;
    cudaGetSymbolAddress((void**)&mu,      g_mu);
    cudaGetSymbolAddress((void**)&lv,      g_lv);
    cudaGetSymbolAddress((void**)&z,       g_z);
    cudaGetSymbolAddress((void**)&q,       g_q);
    cudaGetSymbolAddress((void**)&h,       g_h);
    cudaGetSymbolAddress((void**)&self_em, g_self);
    cudaGetSymbolAddress((void**)&sev,     g_sev);
    cudaGetSymbolAddress((void**)&spa,     g_spa);
    cudaGetSymbolAddress((void**)&oth,     g_other);
    cudaGetSymbolAddress((void**)&kb,      g_k);
    cudaGetSymbolAddress((void**)&vb,      g_v);

    const dim3 blk(256);
    const dim3 gB (HDIM / 64, BATCH / 128);   // M = B       (128 x 64 tiles)
    const dim3 gM (HDIM / 64, MROWS / 128);   // M = B*19

    // mu / log_var
    tgemm<0,0><<<gB, blk>>>(x, OBS, W_mu,  b_mu,  nullptr, 1, mu, BATCH, HDIM, OBS);
    tgemm<0,0><<<gB, blk>>>(x, OBS, W_var, b_var, nullptr, 1, lv, BATCH, HDIM, OBS);
    {
        const int n = BATCH * HDIM;
        z_kernel<<<(n + 255) / 256, 256>>>(eps, mu, lv, z, n);
    }
    // self_em = relu(x[:, :36] @ W_self + b)
    tgemm<0,1><<<gB, blk>>>(x, OBS, W_self, b_self, nullptr, 1, self_em, BATCH, HDIM, SELFD);
    // other_ems = relu(agents @ W_other + b)
    tgemm<1,1><<<gM, blk>>>(x, 0, W_oth, b_oth, nullptr, 1, oth, MROWS, HDIM, OTHD);
    // q = relu(z @ W_q + b)
    tgemm<0,1><<<gB, blk>>>(z, HDIM, W_q, b_q, nullptr, 1, q, BATCH, HDIM, HDIM);
    // k = relu(other_ems @ W_k + b)
    tgemm<0,1><<<gM, blk>>>(oth, HDIM, W_k, b_k, nullptr, 1, kb, MROWS, HDIM, HDIM);
    // sev = self_em @ W_v[256:] + b_v
    tgemm<0,0><<<gB, blk>>>(self_em, HDIM, W_v + HDIM * HDIM, b_v, nullptr, 1, sev, BATCH, HDIM, HDIM);
    // v = relu(other_ems @ W_v[:256] + sev[b])
    tgemm<0,2><<<gM, blk>>>(oth, HDIM, W_v, nullptr, sev, NOTH, vb, MROWS, HDIM, HDIM);
    // attention: scores/softmax/h ; writes att to output
    att_kernel<<<BATCH, 256>>>(q, kb, vb, h, out_att);
    // spa = self_em @ W_a[256:] + b_a
    tgemm<0,0><<<gB, blk>>>(self_em, HDIM, W_a + HDIM * HDIM, b_a, nullptr, 1, spa, BATCH, HDIM, HDIM);
    // out = relu(h @ W_a[:256] + spa[b])
    tgemm<0,2><<<gB, blk>>>(h, HDIM, W_a, nullptr, spa, 1, out_main, BATCH, HDIM, HDIM);
}

// round 7
// speedup vs baseline: 3.0673x; 1.4265x over previous
#include <cuda_runtime.h>
#include <stdint.h>
#include <math.h>

// Problem constants
#define BATCH   16384
#define OBS     568
#define HDIM    256
#define SELFD   36
#define OTHD    28
#define NOTH    19
#define MROWS   (BATCH*NOTH)

// ---------------------------------------------------------------------------
// Scratch (device globals; allocation is forbidden)
// ---------------------------------------------------------------------------
__device__ float g_mu   [BATCH*HDIM];
__device__ float g_lv   [BATCH*HDIM];
__device__ float g_z    [BATCH*HDIM];
__device__ float g_q    [BATCH*HDIM];
__device__ float g_h    [BATCH*HDIM];
__device__ float g_self [BATCH*HDIM];
__device__ float g_sev  [BATCH*HDIM];
__device__ float g_spa  [BATCH*HDIM];
__device__ float g_other[MROWS*HDIM];
__device__ float g_k    [MROWS*HDIM];
__device__ float g_v    [MROWS*HDIM];
__device__ float g_xr   [BATCH*OBS];     // tf32-rounded copy of x
// tf32-rounded weights, ORIGINAL [K][N] layout; packed by element count.
#define WT_MU   0
#define WT_VAR  145408
#define WT_SELF 290816
#define WT_OTH  300032
#define WT_Q    307200
#define WT_K    372736
#define WT_V    438272
#define WT_A    569344
__device__ float g_wt[700416];

// ---------------------------------------------------------------------------
// Helpers
// ---------------------------------------------------------------------------
__device__ __forceinline__ uint32_t smem_u32(const void* p) {
    uint32_t a;
    asm("{ .reg .u64 t; cvta.to.shared.u64 t, %1; cvt.u32.u64 %0, t; }"
        : "=r"(a) : "l"(p));
    return a;
}
__device__ __forceinline__ float rna_tf32(float f) {
    unsigned u;
    asm("cvt.rna.tf32.f32 %0, %1;" : "=r"(u) : "f"(f));
    return __uint_as_float(u);
}
__device__ __forceinline__ void cpa16(uint32_t dst, const float* src, int bytes) {
    asm volatile("cp.async.cg.shared.global [%0], [%1], 16, %2;"
                 :: "r"(dst), "l"(src), "r"(bytes) : "memory");
}

// ---------------------------------------------------------------------------
// TF32 mma.sync GEMM, cp.async 3-stage pipeline.
// C[M,256] = epi(A[M,K] @ W[K,256]); inputs pre-rounded to tf32.
// BM=128, BN=128, BK=32, 256 threads (8 warps 2x4), warp tile 64x32.
// AMAP: 0 = A row = row*lda; 1 = agents view of g_xr
// EPI : 0 = +bias; 1 = relu(+bias); 2 = relu(+extra[(row/rowdiv)*256 + col])
// ROUND: round outputs to tf32 (when C feeds a later GEMM)
// Requires M % 128 == 0 (true everywhere).
// ---------------------------------------------------------------------------
#define GSMEM_BYTES 98304

template<int AMAP, int EPI, int ROUND>
__global__ void __launch_bounds__(256, 2)
tgemm3(const float* __restrict__ A, int lda,
       const float* __restrict__ W,
       const float* __restrict__ bias,
       const float* __restrict__ extra, int rowdiv,
       float* __restrict__ C, int K)
{
    extern __shared__ char sm[];
    const uint32_t sb = smem_u32(sm);
    const int tid  = threadIdx.x;
    const int lane = tid & 31;
    const int wid  = tid >> 5;
    const int wm   = wid >> 2;          // 0..1
    const int wn   = wid & 3;           // 0..3
    const int g    = lane >> 2;         // 0..7
    const int t    = lane & 3;          // 0..3

    const long rowBase = (long)blockIdx.y * 128;
    const int  colBase = blockIdx.x * 128;

    // A producer mapping: 4 chunks of 16B; chunk j covers (m, k0..k0+3)
    int am[4], ak[4]; long abase[4];
#pragma unroll
    for (int j = 0; j < 4; j++) {
        int idx = tid + j * 256;        // 0..1023
        am[j] = idx >> 3;               // 0..127
        ak[j] = (idx & 7) << 2;         // 0,4,...,28
        long row = rowBase + am[j];
        if (AMAP == 0) {
            abase[j] = row * lda;
        } else {
            int bb = (int)(row / NOTH);
            int nn = (int)(row - (long)bb * NOTH);
            abase[j] = (long)bb * OBS + SELFD + nn * OTHD;
        }
    }

    auto issue = [&](int tt, int s) {
        const int kt = tt << 5;
        const uint32_t sA = sb + (uint32_t)s * 32768u;
        const uint32_t sB = sA + 16384u;
        // A: layout word = (k>>2)*512 + m*4 + (k&3)
#pragma unroll
        for (int j = 0; j < 4; j++) {
            int kg  = kt + ak[j];
            int rem = K - kg;
            int bytes = (rem <= 0) ? 0 : ((rem >= 4) ? 16 : rem * 4);
            const float* src = A + abase[j] + (bytes ? kg : 0);
            uint32_t dst = sA + (uint32_t)(((ak[j] >> 2) * 128 + am[j]) * 16);
            cpa16(dst, src, bytes);
        }
        // B: layout word = k*128 + (n ^ ((k&3)<<3))
#pragma unroll
        for (int j = 0; j < 4; j++) {
            int idx = tid + j * 256;    // 0..1023
            int bk  = idx >> 5;         // 0..31
            int bn  = (idx & 31) << 2;  // 0..124
            int kg  = kt + bk;
            int bytes = (kg < K) ? 16 : 0;
            const float* src = W + (long)(bytes ? kg : 0) * 256 + colBase + bn;
            uint32_t dst = sB + (uint32_t)((bk * 128 + (bn ^ ((bk & 3) << 3))) * 4);
            cpa16(dst, src, bytes);
        }
    };

    float acc[4][4][4];
#pragma unroll
    for (int mi = 0; mi < 4; mi++)
#pragma unroll
        for (int ni = 0; ni < 4; ni++)
#pragma unroll
            for (int c = 0; c < 4; c++) acc[mi][ni][c] = 0.f;

    const int nt = (K + 31) >> 5;
#pragma unroll
    for (int s = 0; s < 3; s++) {
        if (s < nt) issue(s, s);
        asm volatile("cp.async.commit_group;" ::: "memory");
    }

    const unsigned* smw = (const unsigned*)sm;
    for (int tt = 0; tt < nt; tt++) {
        asm volatile("cp.async.wait_group 2;" ::: "memory");
        __syncthreads();
        const unsigned* As = smw + (tt % 3) * 8192;
        const unsigned* Bs = As + 4096;
#pragma unroll
        for (int ks = 0; ks < 4; ks++) {
            const int kk = ks * 8;
            unsigned a[4][4], b[4][2];
#pragma unroll
            for (int mi = 0; mi < 4; mi++) {
                const int m0 = wm * 64 + mi * 16 + g;
                a[mi][0] = As[(kk >> 2) * 512 + m0 * 4 + t];
                a[mi][1] = As[(kk >> 2) * 512 + (m0 + 8) * 4 + t];
                a[mi][2] = As[((kk >> 2) + 1) * 512 + m0 * 4 + t];
                a[mi][3] = As[((kk >> 2) + 1) * 512 + (m0 + 8) * 4 + t];
            }
#pragma unroll
            for (int ni = 0; ni < 4; ni++) {
                const int nsw = (wn * 32 + ni * 8 + g) ^ (t << 3);
                b[ni][0] = Bs[(kk + t) * 128 + nsw];
                b[ni][1] = Bs[(kk + t + 4) * 128 + nsw];
            }
#pragma unroll
            for (int mi = 0; mi < 4; mi++)
#pragma unroll
                for (int ni = 0; ni < 4; ni++) {
                    asm volatile(
                        "mma.sync.aligned.m16n8k8.row.col.f32.tf32.tf32.f32 "
                        "{%0,%1,%2,%3},{%4,%5,%6,%7},{%8,%9},{%0,%1,%2,%3};"
                        : "+f"(acc[mi][ni][0]), "+f"(acc[mi][ni][1]),
                          "+f"(acc[mi][ni][2]), "+f"(acc[mi][ni][3])
                        : "r"(a[mi][0]), "r"(a[mi][1]), "r"(a[mi][2]), "r"(a[mi][3]),
                          "r"(b[ni][0]), "r"(b[ni][1]));
                }
        }
        __syncthreads();
        const int tn = tt + 3;
        if (tn < nt) issue(tn, tn % 3);
        asm volatile("cp.async.commit_group;" ::: "memory");
    }

    // ---- epilogue ----
#pragma unroll
    for (int mi = 0; mi < 4; mi++) {
#pragma unroll
        for (int d = 0; d < 2; d++) {
            const long row = rowBase + wm * 64 + mi * 16 + g + d * 8;
            const float* exrow = (EPI == 2) ? (extra + (row / rowdiv) * 256) : nullptr;
#pragma unroll
            for (int ni = 0; ni < 4; ni++) {
                const int col = colBase + wn * 32 + ni * 8 + 2 * t;
                float v0 = acc[mi][ni][2 * d];
                float v1 = acc[mi][ni][2 * d + 1];
                if (EPI == 2) { v0 += exrow[col]; v1 += exrow[col + 1]; }
                else          { v0 += bias[col];  v1 += bias[col + 1]; }
                if (EPI >= 1) { v0 = fmaxf(v0, 0.f); v1 = fmaxf(v1, 0.f); }
                if (ROUND)    { v0 = rna_tf32(v0);   v1 = rna_tf32(v1); }
                *reinterpret_cast<float2*>(&C[row * 256 + col]) = make_float2(v0, v1);
            }
        }
    }
}

// ---------------------------------------------------------------------------
// Round-copy to tf32 (vectorized); n % 4 == 0 at all call sites.
// ---------------------------------------------------------------------------
__global__ void rc_kernel(const float* __restrict__ in, float* __restrict__ out, int n4)
{
    int i = blockIdx.x * blockDim.x + threadIdx.x;
    if (i < n4) {
        float4 v = reinterpret_cast<const float4*>(in)[i];
        v.x = rna_tf32(v.x); v.y = rna_tf32(v.y);
        v.z = rna_tf32(v.z); v.w = rna_tf32(v.w);
        reinterpret_cast<float4*>(out)[i] = v;
    }
}

// ---------------------------------------------------------------------------
// z = round_tf32(eps * exp(0.5*log_var) + mu)
// ---------------------------------------------------------------------------
__global__ void z_kernel(const float* __restrict__ eps,
                         const float* __restrict__ mu,
                         const float* __restrict__ lv,
                         float* __restrict__ z, int n)
{
    int i = blockIdx.x * blockDim.x + threadIdx.x;
    if (i < n) z[i] = rna_tf32(fmaf(eps[i], expf(0.5f * lv[i]), mu[i]));
}

// ---------------------------------------------------------------------------
// Attention: scores = q.k/16 -> softmax(19) -> h = att @ v ; att -> out
// h rounded to tf32 (feeds final GEMM).
// ---------------------------------------------------------------------------
__global__ void __launch_bounds__(256)
att_kernel(const float* __restrict__ q,
           const float* __restrict__ k,
           const float* __restrict__ v,
           float* __restrict__ h,
           float* __restrict__ att_out)
{
    const int b   = blockIdx.x;
    const int tid = threadIdx.x;
    const int wid = tid >> 5;
    const int lane = tid & 31;

    __shared__ float qs[HDIM];
    __shared__ float sc[32];

    qs[tid] = q[(long)b * HDIM + tid];
    __syncthreads();

    for (int n = wid; n < NOTH; n += 8) {
        const float* kp = k + ((long)b * NOTH + n) * HDIM;
        float p = 0.f;
#pragma unroll
        for (int j = 0; j < 8; j++) {
            const int c = lane + 32 * j;
            p = fmaf(qs[c], kp[c], p);
        }
#pragma unroll
        for (int off = 16; off > 0; off >>= 1)
            p += __shfl_xor_sync(0xffffffffu, p, off);
        if (lane == 0) sc[n] = p * 0.0625f;
    }
    __syncthreads();

    if (wid == 0) {
        float s = (lane < NOTH) ? sc[lane] : -INFINITY;
        float m = s;
#pragma unroll
        for (int off = 16; off > 0; off >>= 1)
            m = fmaxf(m, __shfl_xor_sync(0xffffffffu, m, off));
        float e = (lane < NOTH) ? expf(s - m) : 0.f;
        float sum = e;
#pragma unroll
        for (int off = 16; off > 0; off >>= 1)
            sum += __shfl_xor_sync(0xffffffffu, sum, off);
        const float a = e / sum;
        if (lane < NOTH) {
            sc[lane] = a;
            att_out[(long)b * NOTH + lane] = a;
        }
    }
    __syncthreads();

    float acc = 0.f;
    const float* vp = v + (long)b * NOTH * HDIM + tid;
#pragma unroll
    for (int n = 0; n < NOTH; n++)
        acc = fmaf(sc[n], vp[(long)n * HDIM], acc);
    h[(long)b * HDIM + tid] = rna_tf32(acc);
}

// ---------------------------------------------------------------------------
// Launch
// ---------------------------------------------------------------------------
extern "C" void kernel_launch(void* const* d_in, const int* in_sizes, int n_in,
                              void* d_out, int out_size)
{
    const float* x      = (const float*)d_in[0];
    const float* eps    = (const float*)d_in[1];
    const float* W_mu   = (const float*)d_in[2];
    const float* b_mu   = (const float*)d_in[3];
    const float* W_var  = (const float*)d_in[4];
    const float* b_var  = (const float*)d_in[5];
    const float* W_self = (const float*)d_in[6];
    const float* b_self = (const float*)d_in[7];
    const float* W_oth  = (const float*)d_in[8];
    const float* b_oth  = (const float*)d_in[9];
    const float* W_q    = (const float*)d_in[10];
    const float* b_q    = (const float*)d_in[11];
    const float* W_k    = (const float*)d_in[12];
    const float* b_k    = (const float*)d_in[13];
    const float* W_v    = (const float*)d_in[14];
    const float* b_v    = (const float*)d_in[15];
    const float* W_a    = (const float*)d_in[16];
    const float* b_a    = (const float*)d_in[17];

    float* out_main = (float*)d_out;                      // [B,256]
    float* out_att  = (float*)d_out + (long)BATCH * HDIM; // [B,19]

    float *mu, *lv, *z, *q, *h, *self_em, *sev, *spa, *oth, *kb, *vb, *wt, *xr;
    cudaGetSymbolAddress((void**)&mu,      g_mu);
    cudaGetSymbolAddress((void**)&lv,      g_lv);
    cudaGetSymbolAddress((void**)&z,       g_z);
    cudaGetSymbolAddress((void**)&q,       g_q);
    cudaGetSymbolAddress((void**)&h,       g_h);
    cudaGetSymbolAddress((void**)&self_em, g_self);
    cudaGetSymbolAddress((void**)&sev,     g_sev);
    cudaGetSymbolAddress((void**)&spa,     g_spa);
    cudaGetSymbolAddress((void**)&oth,     g_other);
    cudaGetSymbolAddress((void**)&kb,      g_k);
    cudaGetSymbolAddress((void**)&vb,      g_v);
    cudaGetSymbolAddress((void**)&wt,      g_wt);
    cudaGetSymbolAddress((void**)&xr,      g_xr);

    cudaFuncSetAttribute(tgemm3<0,0,0>, cudaFuncAttributeMaxDynamicSharedMemorySize, GSMEM_BYTES);
    cudaFuncSetAttribute(tgemm3<0,1,0>, cudaFuncAttributeMaxDynamicSharedMemorySize, GSMEM_BYTES);
    cudaFuncSetAttribute(tgemm3<0,1,1>, cudaFuncAttributeMaxDynamicSharedMemorySize, GSMEM_BYTES);
    cudaFuncSetAttribute(tgemm3<1,1,1>, cudaFuncAttributeMaxDynamicSharedMemorySize, GSMEM_BYTES);
    cudaFuncSetAttribute(tgemm3<0,2,0>, cudaFuncAttributeMaxDynamicSharedMemorySize, GSMEM_BYTES);

    // tf32 pre-rounding of all GEMM operands
    {
        auto rc = [](const float* src, float* dst, int n) {
            int n4 = n >> 2;
            rc_kernel<<<(n4 + 255) / 256, 256>>>(src, dst, n4);
        };
        rc(W_mu,   wt + WT_MU,   145408);
        rc(W_var,  wt + WT_VAR,  145408);
        rc(W_self, wt + WT_SELF, 9216);
        rc(W_oth,  wt + WT_OTH,  7168);
        rc(W_q,    wt + WT_Q,    65536);
        rc(W_k,    wt + WT_K,    65536);
        rc(W_v,    wt + WT_V,    131072);
        rc(W_a,    wt + WT_A,    131072);
        rc(x,      xr,           BATCH * OBS);
    }

    const dim3 blk(256);
    const dim3 gB(2, BATCH / 128);   // (2, 128)
    const dim3 gM(2, MROWS / 128);   // (2, 2432)

    // mu / log_var / z
    tgemm3<0,0,0><<<gB, blk, GSMEM_BYTES>>>(xr, OBS, wt + WT_MU,  b_mu,  nullptr, 1, mu, OBS);
    tgemm3<0,0,0><<<gB, blk, GSMEM_BYTES>>>(xr, OBS, wt + WT_VAR, b_var, nullptr, 1, lv, OBS);
    {
        const int n = BATCH * HDIM;
        z_kernel<<<(n + 255) / 256, 256>>>(eps, mu, lv, z, n);
    }
    // self_em = relu(x[:, :36] @ W_self + b)   (rounded: feeds sev/spa GEMMs)
    tgemm3<0,1,1><<<gB, blk, GSMEM_BYTES>>>(xr, OBS, wt + WT_SELF, b_self, nullptr, 1, self_em, SELFD);
    // other_ems = relu(agents @ W_other + b)   (rounded: feeds k/v GEMMs)
    tgemm3<1,1,1><<<gM, blk, GSMEM_BYTES>>>(xr, 0, wt + WT_OTH, b_oth, nullptr, 1, oth, OTHD);
    // q = relu(z @ W_q + b)
    tgemm3<0,1,0><<<gB, blk, GSMEM_BYTES>>>(z, HDIM, wt + WT_Q, b_q, nullptr, 1, q, HDIM);
    // k = relu(other_ems @ W_k + b)
    tgemm3<0,1,0><<<gM, blk, GSMEM_BYTES>>>(oth, HDIM, wt + WT_K, b_k, nullptr, 1, kb, HDIM);
    // sev = self_em @ W_v[256:] + b_v
    tgemm3<0,0,0><<<gB, blk, GSMEM_BYTES>>>(self_em, HDIM, wt + WT_V + HDIM * HDIM, b_v, nullptr, 1, sev, HDIM);
    // v = relu(other_ems @ W_v[:256] + sev[b])
    tgemm3<0,2,0><<<gM, blk, GSMEM_BYTES>>>(oth, HDIM, wt + WT_V, nullptr, sev, NOTH, vb, HDIM);
    // attention (writes att to output, h rounded)
    att_kernel<<<BATCH, 256>>>(q, kb, vb, h, out_att);
    // spa = self_em @ W_a[256:] + b_a
    tgemm3<0,0,0><<<gB, blk, GSMEM_BYTES>>>(self_em, HDIM, wt + WT_A + HDIM * HDIM, b_a, nullptr, 1, spa, HDIM);
    // out = relu(h @ W_a[:256] + spa[b])
    tgemm3<0,2,0><<<gB, blk, GSMEM_BYTES>>>(h, HDIM, wt + WT_A, nullptr, spa, 1, out_main, HDIM);
}

// round 8
// speedup vs baseline: 3.6597x; 1.1932x over previous
#include <cuda_runtime.h>
#include <stdint.h>
#include <math.h>

// Problem constants
#define BATCH   16384
#define OBS     568
#define HDIM    256
#define SELFD   36
#define OTHD    28
#define NOTH    19
#define MROWS   (BATCH*NOTH)

// ---------------------------------------------------------------------------
// Scratch (device globals; allocation is forbidden)
// ---------------------------------------------------------------------------
__device__ float g_mu   [BATCH*HDIM];
__device__ float g_z    [BATCH*HDIM];
__device__ float g_q    [BATCH*HDIM];
__device__ float g_h    [BATCH*HDIM];
__device__ float g_self [BATCH*HDIM];
__device__ float g_sev  [BATCH*HDIM];
__device__ float g_spa  [BATCH*HDIM];
__device__ float g_k    [MROWS*HDIM];
__device__ float g_v    [MROWS*HDIM];
__device__ float g_xr   [BATCH*OBS];     // tf32-rounded copy of x
// tf32-rounded weights, ORIGINAL [K][N] layout; packed by element count.
#define WT_MU   0
#define WT_VAR  145408
#define WT_SELF 290816
#define WT_OTH  300032
#define WT_Q    307200
#define WT_K    372736
#define WT_V    438272
#define WT_A    569344
__device__ float g_wt[700416];

// ---------------------------------------------------------------------------
// Helpers
// ---------------------------------------------------------------------------
__device__ __forceinline__ uint32_t smem_u32(const void* p) {
    uint32_t a;
    asm("{ .reg .u64 t; cvta.to.shared.u64 t, %1; cvt.u32.u64 %0, t; }"
        : "=r"(a) : "l"(p));
    return a;
}
__device__ __forceinline__ float rna_tf32(float f) {
    unsigned u;
    asm("cvt.rna.tf32.f32 %0, %1;" : "=r"(u) : "f"(f));
    return __uint_as_float(u);
}
__device__ __forceinline__ void cpa16(uint32_t dst, const float* src, int bytes) {
    asm volatile("cp.async.cg.shared.global [%0], [%1], 16, %2;"
                 :: "r"(dst), "l"(src), "r"(bytes) : "memory");
}
#define MMA_TF32(acc, a, b) \
    asm volatile( \
        "mma.sync.aligned.m16n8k8.row.col.f32.tf32.tf32.f32 " \
        "{%0,%1,%2,%3},{%4,%5,%6,%7},{%8,%9},{%0,%1,%2,%3};" \
        : "+f"((acc)[0]), "+f"((acc)[1]), "+f"((acc)[2]), "+f"((acc)[3]) \
        : "r"((a)[0]), "r"((a)[1]), "r"((a)[2]), "r"((a)[3]), \
          "r"((b)[0]), "r"((b)[1]))

// ---------------------------------------------------------------------------
// TF32 mma.sync GEMM, cp.async 3-stage pipeline.
// C[M,256] = epi(A[M,K] @ W[K,256]); inputs pre-rounded to tf32.
// BM=128, BN=128, BK=32, 256 threads (8 warps 2x4), warp tile 64x32.
// EPI : 0 = +bias; 1 = relu(+bias); 2 = relu(+extra[(row/rowdiv)*256+col]);
//       3 = z-fusion: lv=acc+bias; C = rna(fma(aux, exp(0.5*lv), extra)) per elem
// ROUND: round outputs to tf32 (when C feeds a later GEMM)
// ---------------------------------------------------------------------------
#define GSMEM_BYTES 98304

template<int EPI, int ROUND>
__global__ void __launch_bounds__(256, 2)
tgemm3(const float* __restrict__ A, int lda,
       const float* __restrict__ W,
       const float* __restrict__ bias,
       const float* __restrict__ extra, int rowdiv,
       const float* __restrict__ aux,
       float* __restrict__ C, int K)
{
    extern __shared__ char sm[];
    const uint32_t sb = smem_u32(sm);
    const int tid  = threadIdx.x;
    const int lane = tid & 31;
    const int wid  = tid >> 5;
    const int wm   = wid >> 2;
    const int wn   = wid & 3;
    const int g    = lane >> 2;
    const int t    = lane & 3;

    const long rowBase = (long)blockIdx.y * 128;
    const int  colBase = blockIdx.x * 128;

    int am[4], ak[4]; long abase[4];
#pragma unroll
    for (int j = 0; j < 4; j++) {
        int idx = tid + j * 256;
        am[j] = idx >> 3;
        ak[j] = (idx & 7) << 2;
        abase[j] = (rowBase + am[j]) * (long)lda;
    }

    auto issue = [&](int tt, int s) {
        const int kt = tt << 5;
        const uint32_t sA = sb + (uint32_t)s * 32768u;
        const uint32_t sB = sA + 16384u;
#pragma unroll
        for (int j = 0; j < 4; j++) {
            int kg  = kt + ak[j];
            int rem = K - kg;
            int bytes = (rem <= 0) ? 0 : ((rem >= 4) ? 16 : rem * 4);
            const float* src = A + abase[j] + (bytes ? kg : 0);
            uint32_t dst = sA + (uint32_t)(((ak[j] >> 2) * 128 + am[j]) * 16);
            cpa16(dst, src, bytes);
        }
#pragma unroll
        for (int j = 0; j < 4; j++) {
            int idx = tid + j * 256;
            int bk  = idx >> 5;
            int bn  = (idx & 31) << 2;
            int kg  = kt + bk;
            int bytes = (kg < K) ? 16 : 0;
            const float* src = W + (long)(bytes ? kg : 0) * 256 + colBase + bn;
            uint32_t dst = sB + (uint32_t)((bk * 128 + (bn ^ ((bk & 3) << 3))) * 4);
            cpa16(dst, src, bytes);
        }
    };

    float acc[4][4][4];
#pragma unroll
    for (int mi = 0; mi < 4; mi++)
#pragma unroll
        for (int ni = 0; ni < 4; ni++)
#pragma unroll
            for (int c = 0; c < 4; c++) acc[mi][ni][c] = 0.f;

    const int nt = (K + 31) >> 5;
#pragma unroll
    for (int s = 0; s < 3; s++) {
        if (s < nt) issue(s, s);
        asm volatile("cp.async.commit_group;" ::: "memory");
    }

    const unsigned* smw = (const unsigned*)sm;
    for (int tt = 0; tt < nt; tt++) {
        asm volatile("cp.async.wait_group 2;" ::: "memory");
        __syncthreads();
        const unsigned* As = smw + (tt % 3) * 8192;
        const unsigned* Bs = As + 4096;
#pragma unroll
        for (int ks = 0; ks < 4; ks++) {
            const int kk = ks * 8;
            unsigned a[4][4], b[4][2];
#pragma unroll
            for (int mi = 0; mi < 4; mi++) {
                const int m0 = wm * 64 + mi * 16 + g;
                a[mi][0] = As[(kk >> 2) * 512 + m0 * 4 + t];
                a[mi][1] = As[(kk >> 2) * 512 + (m0 + 8) * 4 + t];
                a[mi][2] = As[((kk >> 2) + 1) * 512 + m0 * 4 + t];
                a[mi][3] = As[((kk >> 2) + 1) * 512 + (m0 + 8) * 4 + t];
            }
#pragma unroll
            for (int ni = 0; ni < 4; ni++) {
                const int nsw = (wn * 32 + ni * 8 + g) ^ (t << 3);
                b[ni][0] = Bs[(kk + t) * 128 + nsw];
                b[ni][1] = Bs[(kk + t + 4) * 128 + nsw];
            }
#pragma unroll
            for (int mi = 0; mi < 4; mi++)
#pragma unroll
                for (int ni = 0; ni < 4; ni++)
                    MMA_TF32(acc[mi][ni], a[mi], b[ni]);
        }
        __syncthreads();
        const int tn = tt + 3;
        if (tn < nt) issue(tn, tn % 3);
        asm volatile("cp.async.commit_group;" ::: "memory");
    }

#pragma unroll
    for (int mi = 0; mi < 4; mi++) {
#pragma unroll
        for (int d = 0; d < 2; d++) {
            const long row = rowBase + wm * 64 + mi * 16 + g + d * 8;
            const float* exrow = (EPI == 2) ? (extra + (row / rowdiv) * 256) : nullptr;
#pragma unroll
            for (int ni = 0; ni < 4; ni++) {
                const int col = colBase + wn * 32 + ni * 8 + 2 * t;
                float v0 = acc[mi][ni][2 * d];
                float v1 = acc[mi][ni][2 * d + 1];
                if (EPI == 3) {
                    v0 += bias[col]; v1 += bias[col + 1];
                    const float* murow  = extra + row * 256;
                    const float* epsrow = aux + row * 256;
                    v0 = rna_tf32(fmaf(epsrow[col],     expf(0.5f * v0), murow[col]));
                    v1 = rna_tf32(fmaf(epsrow[col + 1], expf(0.5f * v1), murow[col + 1]));
                } else {
                    if (EPI == 2) { v0 += exrow[col]; v1 += exrow[col + 1]; }
                    else          { v0 += bias[col];  v1 += bias[col + 1]; }
                    if (EPI >= 1) { v0 = fmaxf(v0, 0.f); v1 = fmaxf(v1, 0.f); }
                    if (ROUND)    { v0 = rna_tf32(v0);   v1 = rna_tf32(v1); }
                }
                *reinterpret_cast<float2*>(&C[row * 256 + col]) = make_float2(v0, v1);
            }
        }
    }
}

// ---------------------------------------------------------------------------
// Fused oth -> (k, v): per CTA, 128 agent rows.
// Stage 1: oth = rna(relu(agents[128,28] @ W_oth + b)) -> smem (A-layout)
// Stage 2: 4 chunks {k-lo, k-hi, v-lo, v-hi}: K=256 GEMM, A from smem,
//          W via 3-stage cp.async; k: relu(+b_k); v: relu(+sev[batch]).
// 512 threads (16 warps, 4x4), warp tile 32x32. 192 KB smem, 1 CTA/SM.
// ---------------------------------------------------------------------------
#define FSMEM_BYTES 196608
#define OTH_W  0          // 128x256 A-layout: word (k>>2)*512 + m*4 + (k&3)
#define STG_W  32768      // 3 stages x 4096 words (32x128 B tiles, swizzled)
#define A1_W   45056      // agents tile 128x32, A-layout

__global__ void __launch_bounds__(512, 1)
fused_okv(const float* __restrict__ xr,
          const float* __restrict__ Woth, const float* __restrict__ both,
          const float* __restrict__ Wk,   const float* __restrict__ bk_,
          const float* __restrict__ Wv,
          const float* __restrict__ sev,
          float* __restrict__ kb, float* __restrict__ vb)
{
    extern __shared__ char sm[];
    unsigned* smw = (unsigned*)sm;
    float*    smf = (float*)sm;
    const uint32_t sb = smem_u32(sm);
    const int tid  = threadIdx.x;
    const int lane = tid & 31;
    const int wid  = tid >> 5;
    const int wm   = wid >> 2;   // 0..3
    const int wn   = wid & 3;    // 0..3
    const int g    = lane >> 2;
    const int t    = lane & 3;
    const long rowBase = (long)blockIdx.x * 128;

    // ---- stage 1 loads: agents A tile + W_oth halves into stages 0,1 ----
#pragma unroll
    for (int j = 0; j < 2; j++) {
        int idx = tid + j * 512;
        int m = idx >> 3, k0 = (idx & 7) << 2;
        long row = rowBase + m;
        int bb = (int)(row / NOTH);
        int nn = (int)(row - (long)bb * NOTH);
        long abase = (long)bb * OBS + SELFD + nn * OTHD;
        int rem = OTHD - k0;
        int bytes = (rem <= 0) ? 0 : ((rem >= 4) ? 16 : rem * 4);
        cpa16(sb + (uint32_t)((A1_W + (k0 >> 2) * 512 + m * 4) * 4),
              xr + abase + (bytes ? k0 : 0), bytes);
    }
#pragma unroll
    for (int h = 0; h < 2; h++)
#pragma unroll
    for (int j = 0; j < 2; j++) {
        int idx = tid + j * 512;
        int bk = idx >> 5, bn = (idx & 31) << 2;
        int bytes = (bk < OTHD) ? 16 : 0;
        const float* src = Woth + (long)(bytes ? bk : 0) * 256 + h * 128 + bn;
        cpa16(sb + (uint32_t)((STG_W + h * 4096 + bk * 128 + (bn ^ ((bk & 3) << 3))) * 4),
              src, bytes);
    }
    asm volatile("cp.async.commit_group;" ::: "memory");
    asm volatile("cp.async.wait_group 0;" ::: "memory");
    __syncthreads();

    // ---- stage 1 compute ----
    for (int h = 0; h < 2; h++) {
        float acc[2][4][4];
#pragma unroll
        for (int mi = 0; mi < 2; mi++)
#pragma unroll
            for (int ni = 0; ni < 4; ni++)
#pragma unroll
                for (int c = 0; c < 4; c++) acc[mi][ni][c] = 0.f;
        const unsigned* As = smw + A1_W;
        const unsigned* Bs = smw + STG_W + h * 4096;
#pragma unroll
        for (int ks = 0; ks < 4; ks++) {
            const int kk = ks * 8;
            unsigned a[2][4], b[4][2];
#pragma unroll
            for (int mi = 0; mi < 2; mi++) {
                const int m0 = wm * 32 + mi * 16 + g;
                a[mi][0] = As[(kk >> 2) * 512 + m0 * 4 + t];
                a[mi][1] = As[(kk >> 2) * 512 + (m0 + 8) * 4 + t];
                a[mi][2] = As[((kk >> 2) + 1) * 512 + m0 * 4 + t];
                a[mi][3] = As[((kk >> 2) + 1) * 512 + (m0 + 8) * 4 + t];
            }
#pragma unroll
            for (int ni = 0; ni < 4; ni++) {
                const int nsw = (wn * 32 + ni * 8 + g) ^ (t << 3);
                b[ni][0] = Bs[(kk + t) * 128 + nsw];
                b[ni][1] = Bs[(kk + t + 4) * 128 + nsw];
            }
#pragma unroll
            for (int mi = 0; mi < 2; mi++)
#pragma unroll
                for (int ni = 0; ni < 4; ni++)
                    MMA_TF32(acc[mi][ni], a[mi], b[ni]);
        }
        // epilogue -> OTH_S (A-layout, col of oth = k of stage 2)
#pragma unroll
        for (int mi = 0; mi < 2; mi++)
#pragma unroll
            for (int d = 0; d < 2; d++) {
                const int rm = wm * 32 + mi * 16 + g + d * 8;
#pragma unroll
                for (int ni = 0; ni < 4; ni++)
#pragma unroll
                    for (int e = 0; e < 2; e++) {
                        const int col = h * 128 + wn * 32 + ni * 8 + 2 * t + e;
                        float v = rna_tf32(fmaxf(acc[mi][ni][2 * d + e] + both[col], 0.f));
                        smf[OTH_W + (col >> 2) * 512 + rm * 4 + (col & 3)] = v;
                    }
            }
    }
    __syncthreads();

    // ---- stage 2: 4 chunks ----
    for (int cc = 0; cc < 4; cc++) {
        const float* W = (cc < 2) ? Wk : Wv;
        const int colOff = (cc & 1) * 128;
        float* Co = (cc < 2) ? kb : vb;

        auto issueB = [&](int tt, int s) {
#pragma unroll
            for (int j = 0; j < 2; j++) {
                int idx = tid + j * 512;
                int bk = idx >> 5, bn = (idx & 31) << 2;
                cpa16(sb + (uint32_t)((STG_W + s * 4096 + bk * 128 + (bn ^ ((bk & 3) << 3))) * 4),
                      W + (long)(tt * 32 + bk) * 256 + colOff + bn, 16);
            }
        };

        float acc[2][4][4];
#pragma unroll
        for (int mi = 0; mi < 2; mi++)
#pragma unroll
            for (int ni = 0; ni < 4; ni++)
#pragma unroll
                for (int c = 0; c < 4; c++) acc[mi][ni][c] = 0.f;

#pragma unroll
        for (int s = 0; s < 3; s++) {
            issueB(s, s);
            asm volatile("cp.async.commit_group;" ::: "memory");
        }

        for (int tt = 0; tt < 8; tt++) {
            asm volatile("cp.async.wait_group 2;" ::: "memory");
            __syncthreads();
            const unsigned* As = smw + OTH_W;
            const unsigned* Bs = smw + STG_W + (tt % 3) * 4096;
#pragma unroll
            for (int ks = 0; ks < 4; ks++) {
                const int kk = ks * 8;
                const int kq = tt * 8 + ks * 2;
                unsigned a[2][4], b[4][2];
#pragma unroll
                for (int mi = 0; mi < 2; mi++) {
                    const int m0 = wm * 32 + mi * 16 + g;
                    a[mi][0] = As[kq * 512 + m0 * 4 + t];
                    a[mi][1] = As[kq * 512 + (m0 + 8) * 4 + t];
                    a[mi][2] = As[(kq + 1) * 512 + m0 * 4 + t];
                    a[mi][3] = As[(kq + 1) * 512 + (m0 + 8) * 4 + t];
                }
#pragma unroll
                for (int ni = 0; ni < 4; ni++) {
                    const int nsw = (wn * 32 + ni * 8 + g) ^ (t << 3);
                    b[ni][0] = Bs[(kk + t) * 128 + nsw];
                    b[ni][1] = Bs[(kk + t + 4) * 128 + nsw];
                }
#pragma unroll
                for (int mi = 0; mi < 2; mi++)
#pragma unroll
                    for (int ni = 0; ni < 4; ni++)
                        MMA_TF32(acc[mi][ni], a[mi], b[ni]);
            }
            __syncthreads();
            if (tt + 3 < 8) issueB(tt + 3, (tt + 3) % 3);
            asm volatile("cp.async.commit_group;" ::: "memory");
        }

        // epilogue
#pragma unroll
        for (int mi = 0; mi < 2; mi++)
#pragma unroll
            for (int d = 0; d < 2; d++) {
                const long row = rowBase + wm * 32 + mi * 16 + g + d * 8;
                const float* sv = (cc >= 2) ? (sev + (row / NOTH) * 256) : nullptr;
#pragma unroll
                for (int ni = 0; ni < 4; ni++) {
                    const int col = colOff + wn * 32 + ni * 8 + 2 * t;
                    float v0 = acc[mi][ni][2 * d];
                    float v1 = acc[mi][ni][2 * d + 1];
                    if (cc < 2) { v0 += bk_[col]; v1 += bk_[col + 1]; }
                    else        { v0 += sv[col];  v1 += sv[col + 1]; }
                    v0 = fmaxf(v0, 0.f); v1 = fmaxf(v1, 0.f);
                    *reinterpret_cast<float2*>(&Co[row * 256 + col]) = make_float2(v0, v1);
                }
            }
    }
}

// ---------------------------------------------------------------------------
// Round-copy to tf32 (vectorized); n % 4 == 0 at all call sites.
// ---------------------------------------------------------------------------
__global__ void rc_kernel(const float* __restrict__ in, float* __restrict__ out, int n4)
{
    int i = blockIdx.x * blockDim.x + threadIdx.x;
    if (i < n4) {
        float4 v = reinterpret_cast<const float4*>(in)[i];
        v.x = rna_tf32(v.x); v.y = rna_tf32(v.y);
        v.z = rna_tf32(v.z); v.w = rna_tf32(v.w);
        reinterpret_cast<float4*>(out)[i] = v;
    }
}

// ---------------------------------------------------------------------------
// Attention: scores = q.k/16 -> softmax(19) -> h = att @ v ; att -> out
// ---------------------------------------------------------------------------
__global__ void __launch_bounds__(256)
att_kernel(const float* __restrict__ q,
           const float* __restrict__ k,
           const float* __restrict__ v,
           float* __restrict__ h,
           float* __restrict__ att_out)
{
    const int b   = blockIdx.x;
    const int tid = threadIdx.x;
    const int wid = tid >> 5;
    const int lane = tid & 31;

    __shared__ float qs[HDIM];
    __shared__ float sc[32];

    qs[tid] = q[(long)b * HDIM + tid];
    __syncthreads();

    for (int n = wid; n < NOTH; n += 8) {
        const float* kp = k + ((long)b * NOTH + n) * HDIM;
        float p = 0.f;
#pragma unroll
        for (int j = 0; j < 8; j++) {
            const int c = lane + 32 * j;
            p = fmaf(qs[c], kp[c], p);
        }
#pragma unroll
        for (int off = 16; off > 0; off >>= 1)
            p += __shfl_xor_sync(0xffffffffu, p, off);
        if (lane == 0) sc[n] = p * 0.0625f;
    }
    __syncthreads();

    if (wid == 0) {
        float s = (lane < NOTH) ? sc[lane] : -INFINITY;
        float m = s;
#pragma unroll
        for (int off = 16; off > 0; off >>= 1)
            m = fmaxf(m, __shfl_xor_sync(0xffffffffu, m, off));
        float e = (lane < NOTH) ? expf(s - m) : 0.f;
        float sum = e;
#pragma unroll
        for (int off = 16; off > 0; off >>= 1)
            sum += __shfl_xor_sync(0xffffffffu, sum, off);
        const float a = e / sum;
        if (lane < NOTH) {
            sc[lane] = a;
            att_out[(long)b * NOTH + lane] = a;
        }
    }
    __syncthreads();

    float acc = 0.f;
    const float* vp = v + (long)b * NOTH * HDIM + tid;
#pragma unroll
    for (int n = 0; n < NOTH; n++)
        acc = fmaf(sc[n], vp[(long)n * HDIM], acc);
    h[(long)b * HDIM + tid] = rna_tf32(acc);
}

// ---------------------------------------------------------------------------
// Launch
// ---------------------------------------------------------------------------
extern "C" void kernel_launch(void* const* d_in, const int* in_sizes, int n_in,
                              void* d_out, int out_size)
{
    const float* x      = (const float*)d_in[0];
    const float* eps    = (const float*)d_in[1];
    const float* W_mu   = (const float*)d_in[2];
    const float* b_mu   = (const float*)d_in[3];
    const float* W_var  = (const float*)d_in[4];
    const float* b_var  = (const float*)d_in[5];
    const float* W_self = (const float*)d_in[6];
    const float* b_self = (const float*)d_in[7];
    const float* W_oth  = (const float*)d_in[8];
    const float* b_oth  = (const float*)d_in[9];
    const float* W_q    = (const float*)d_in[10];
    const float* b_q    = (const float*)d_in[11];
    const float* W_k    = (const float*)d_in[12];
    const float* b_k    = (const float*)d_in[13];
    const float* W_v    = (const float*)d_in[14];
    const float* b_v    = (const float*)d_in[15];
    const float* W_a    = (const float*)d_in[16];
    const float* b_a    = (const float*)d_in[17];

    float* out_main = (float*)d_out;                      // [B,256]
    float* out_att  = (float*)d_out + (long)BATCH * HDIM; // [B,19]

    float *mu, *z, *q, *h, *self_em, *sev, *spa, *kb, *vb, *wt, *xr;
    cudaGetSymbolAddress((void**)&mu,      g_mu);
    cudaGetSymbolAddress((void**)&z,       g_z);
    cudaGetSymbolAddress((void**)&q,       g_q);
    cudaGetSymbolAddress((void**)&h,       g_h);
    cudaGetSymbolAddress((void**)&self_em, g_self);
    cudaGetSymbolAddress((void**)&sev,     g_sev);
    cudaGetSymbolAddress((void**)&spa,     g_spa);
    cudaGetSymbolAddress((void**)&kb,      g_k);
    cudaGetSymbolAddress((void**)&vb,      g_v);
    cudaGetSymbolAddress((void**)&wt,      g_wt);
    cudaGetSymbolAddress((void**)&xr,      g_xr);

    cudaFuncSetAttribute(tgemm3<0,0>, cudaFuncAttributeMaxDynamicSharedMemorySize, GSMEM_BYTES);
    cudaFuncSetAttribute(tgemm3<1,0>, cudaFuncAttributeMaxDynamicSharedMemorySize, GSMEM_BYTES);
    cudaFuncSetAttribute(tgemm3<1,1>, cudaFuncAttributeMaxDynamicSharedMemorySize, GSMEM_BYTES);
    cudaFuncSetAttribute(tgemm3<2,0>, cudaFuncAttributeMaxDynamicSharedMemorySize, GSMEM_BYTES);
    cudaFuncSetAttribute(tgemm3<3,0>, cudaFuncAttributeMaxDynamicSharedMemorySize, GSMEM_BYTES);
    cudaFuncSetAttribute(fused_okv,   cudaFuncAttributeMaxDynamicSharedMemorySize, FSMEM_BYTES);

    // tf32 pre-rounding of all GEMM operands
    {
        auto rc = [](const float* src, float* dst, int n) {
            int n4 = n >> 2;
            rc_kernel<<<(n4 + 255) / 256, 256>>>(src, dst, n4);
        };
        rc(W_mu,   wt + WT_MU,   145408);
        rc(W_var,  wt + WT_VAR,  145408);
        rc(W_self, wt + WT_SELF, 9216);
        rc(W_oth,  wt + WT_OTH,  7168);
        rc(W_q,    wt + WT_Q,    65536);
        rc(W_k,    wt + WT_K,    65536);
        rc(W_v,    wt + WT_V,    131072);
        rc(W_a,    wt + WT_A,    131072);
        rc(x,      xr,           BATCH * OBS);
    }

    const dim3 blk(256);
    const dim3 gB(2, BATCH / 128);   // (2, 128)

    // mu = x @ W_mu + b_mu
    tgemm3<0,0><<<gB, blk, GSMEM_BYTES>>>(xr, OBS, wt + WT_MU,  b_mu,  nullptr, 1, nullptr, mu, OBS);
    // z = rna(eps * exp(0.5*(x@W_var+b_var)) + mu)   [fused into log_var GEMM]
    tgemm3<3,0><<<gB, blk, GSMEM_BYTES>>>(xr, OBS, wt + WT_VAR, b_var, mu, 1, eps, z, OBS);
    // self_em = rna(relu(x[:, :36] @ W_self + b))
    tgemm3<1,1><<<gB, blk, GSMEM_BYTES>>>(xr, OBS, wt + WT_SELF, b_self, nullptr, 1, nullptr, self_em, SELFD);
    // sev = self_em @ W_v[256:] + b_v
    tgemm3<0,0><<<gB, blk, GSMEM_BYTES>>>(self_em, HDIM, wt + WT_V + HDIM * HDIM, b_v, nullptr, 1, nullptr, sev, HDIM);
    // fused: oth (smem) -> k, v
    fused_okv<<<MROWS / 128, 512, FSMEM_BYTES>>>(xr, wt + WT_OTH, b_oth,
                                                 wt + WT_K, b_k, wt + WT_V,
                                                 sev, kb, vb);
    // q = relu(z @ W_q + b)
    tgemm3<1,0><<<gB, blk, GSMEM_BYTES>>>(z, HDIM, wt + WT_Q, b_q, nullptr, 1, nullptr, q, HDIM);
    // attention (writes att to output, h rounded)
    att_kernel<<<BATCH, 256>>>(q, kb, vb, h, out_att);
    // spa = self_em @ W_a[256:] + b_a
    tgemm3<0,0><<<gB, blk, GSMEM_BYTES>>>(self_em, HDIM, wt + WT_A + HDIM * HDIM, b_a, nullptr, 1, nullptr, spa, HDIM);
    // out = relu(h @ W_a[:256] + spa[b])
    tgemm3<2,0><<<gB, blk, GSMEM_BYTES>>>(h, HDIM, wt + WT_A, nullptr, spa, 1, nullptr, out_main, HDIM);
}

// round 11
// speedup vs baseline: 6.1655x; 1.6847x over previous
#include <cuda_runtime.h>
#include <cuda_fp16.h>
#include <stdint.h>
#include <math.h>

// Problem constants
#define BATCH   16384
#define OBS     568
#define HDIM    256
#define SELFD   36
#define OTHD    28
#define NOTH    19
#define MROWS   (BATCH*NOTH)
#define XWP     284          // OBS/2 half2 words per x row

// ---------------------------------------------------------------------------
// Scratch (device globals; allocation is forbidden)
// ---------------------------------------------------------------------------
__device__ float   g_mu  [BATCH*HDIM];
__device__ float   g_q   [BATCH*HDIM];
__device__ float   g_sev [BATCH*HDIM];
__device__ float   g_spa [BATCH*HDIM];
__device__ __half2 g_zh  [BATCH*128];
__device__ __half2 g_selfh[BATCH*128];
__device__ __half2 g_hh  [BATCH*128];
__device__ __half2 g_kh  [MROWS*128];
__device__ __half2 g_vh  [MROWS*128];
__device__ __half2 g_xh  [BATCH*XWP];
// Packed weights [Kp][256] half2 (lo = even k, hi = odd k). Word offsets:
#define WT2_MU   0
#define WT2_VAR  72704
#define WT2_SELF 145408
#define WT2_OTH  150016
#define WT2_Q    153600
#define WT2_K    186368
#define WT2_V    219136
#define WT2_A    284672
__device__ __half2 g_wp[350208];

// ---------------------------------------------------------------------------
// Helpers
// ---------------------------------------------------------------------------
__device__ __forceinline__ uint32_t smem_u32(const void* p) {
    uint32_t a;
    asm("{ .reg .u64 t; cvta.to.shared.u64 t, %1; cvt.u32.u64 %0, t; }"
        : "=r"(a) : "l"(p));
    return a;
}
__device__ __forceinline__ void cpa16(uint32_t dst, const void* src, int bytes) {
    asm volatile("cp.async.cg.shared.global [%0], [%1], 16, %2;"
                 :: "r"(dst), "l"(src), "r"(bytes) : "memory");
}
#define MMA_F16(acc, a, b) \
    asm volatile( \
        "mma.sync.aligned.m16n8k16.row.col.f32.f16.f16.f32 " \
        "{%0,%1,%2,%3},{%4,%5,%6,%7},{%8,%9},{%0,%1,%2,%3};" \
        : "+f"((acc)[0]), "+f"((acc)[1]), "+f"((acc)[2]), "+f"((acc)[3]) \
        : "r"((a)[0]), "r"((a)[1]), "r"((a)[2]), "r"((a)[3]), \
          "r"((b)[0]), "r"((b)[1]))

// ---------------------------------------------------------------------------
// FP16 mma.sync GEMM, cp.async 3-stage pipeline.
// C[M,256] = epi(A[M,2*Kp] @ W[2*Kp,256]); operands half2 kp-packed.
// BM=128, BN=128, BKp=16 (K=32), 256 threads (8 warps 2x4), warp tile 64x32.
// EPI : 0 = +bias; 1 = relu(+bias); 2 = relu(+extra[row*256+col]);
//       3 = z-fusion: lv=acc+bias; C = fma(aux, exp(0.5*lv), extra) per elem
// OUTH: 1 = write half2-packed Ch[row*128+col/2]; 0 = write fp32 Cf.
// ---------------------------------------------------------------------------
#define GSMEM_BYTES 49152

template<int EPI, int OUTH>
__global__ void __launch_bounds__(256, 2)
hgemm(const __half2* __restrict__ A, int lda,          // lda in half2 words
      const __half2* __restrict__ W,                   // [Kp][256] words
      const float* __restrict__ bias,
      const float* __restrict__ extra,
      const float* __restrict__ aux,
      float* __restrict__ Cf, __half2* __restrict__ Ch,
      int Kp)
{
    extern __shared__ char sm[];
    const uint32_t sb = smem_u32(sm);
    const int tid  = threadIdx.x;
    const int lane = tid & 31;
    const int wid  = tid >> 5;
    const int wm   = wid >> 2;
    const int wn   = wid & 3;
    const int g    = lane >> 2;
    const int t    = lane & 3;

    const long rowBase = (long)blockIdx.y * 128;
    const int  colBase = blockIdx.x * 128;

    // A producer: 2 chunks of 16B (4 half2 words) each
    int am[2], aw[2]; long abase[2];
#pragma unroll
    for (int j = 0; j < 2; j++) {
        int idx = tid + j * 256;     // 0..511
        am[j] = idx >> 2;            // 0..127
        aw[j] = (idx & 3) << 2;      // 0,4,8,12 (kp word offset)
        abase[j] = (rowBase + am[j]) * (long)lda;
    }

    auto issue = [&](int tt, int s) {
        const int ktp = tt << 4;
        const uint32_t sA = sb + (uint32_t)s * 16384u;
        const uint32_t sB = sA + 8192u;
#pragma unroll
        for (int j = 0; j < 2; j++) {
            int kg  = ktp + aw[j];
            int rem = Kp - kg;
            int bytes = (rem <= 0) ? 0 : ((rem >= 4) ? 16 : rem * 4);
            const __half2* src = A + abase[j] + (bytes ? kg : 0);
            uint32_t dst = sA + (uint32_t)(((aw[j] >> 2) * 512 + am[j] * 4) * 4);
            cpa16(dst, src, bytes);
        }
#pragma unroll
        for (int j = 0; j < 2; j++) {
            int idx = tid + j * 256;
            int bkp = idx >> 5;           // 0..15
            int bn  = (idx & 31) << 2;    // 0..124
            int kg  = ktp + bkp;
            int bytes = (kg < Kp) ? 16 : 0;
            const __half2* src = W + (long)(bytes ? kg : 0) * 256 + colBase + bn;
            uint32_t dst = sB + (uint32_t)((bkp * 128 + (bn ^ ((bkp & 3) << 3))) * 4);
            cpa16(dst, src, bytes);
        }
    };

    float acc[4][4][4];
#pragma unroll
    for (int mi = 0; mi < 4; mi++)
#pragma unroll
        for (int ni = 0; ni < 4; ni++)
#pragma unroll
            for (int c = 0; c < 4; c++) acc[mi][ni][c] = 0.f;

    const int nt = (Kp + 15) >> 4;
#pragma unroll
    for (int s = 0; s < 3; s++) {
        if (s < nt) issue(s, s);
        asm volatile("cp.async.commit_group;" ::: "memory");
    }

    const unsigned* smw = (const unsigned*)sm;
    for (int tt = 0; tt < nt; tt++) {
        asm volatile("cp.async.wait_group 2;" ::: "memory");
        __syncthreads();
        const unsigned* As = smw + (tt % 3) * 4096;
        const unsigned* Bs = As + 2048;
#pragma unroll
        for (int ks = 0; ks < 2; ks++) {
            unsigned a[4][4], b[4][2];
#pragma unroll
            for (int mi = 0; mi < 4; mi++) {
                const int m0 = wm * 64 + mi * 16 + g;
                a[mi][0] = As[(2 * ks) * 512 + m0 * 4 + t];
                a[mi][1] = As[(2 * ks) * 512 + (m0 + 8) * 4 + t];
                a[mi][2] = As[(2 * ks + 1) * 512 + m0 * 4 + t];
                a[mi][3] = As[(2 * ks + 1) * 512 + (m0 + 8) * 4 + t];
            }
#pragma unroll
            for (int ni = 0; ni < 4; ni++) {
                const int nsw = (wn * 32 + ni * 8 + g) ^ (t << 3);
                b[ni][0] = Bs[(ks * 8 + t) * 128 + nsw];
                b[ni][1] = Bs[(ks * 8 + t + 4) * 128 + nsw];
            }
#pragma unroll
            for (int mi = 0; mi < 4; mi++)
#pragma unroll
                for (int ni = 0; ni < 4; ni++)
                    MMA_F16(acc[mi][ni], a[mi], b[ni]);
        }
        __syncthreads();
        const int tn = tt + 3;
        if (tn < nt) issue(tn, tn % 3);
        asm volatile("cp.async.commit_group;" ::: "memory");
    }

#pragma unroll
    for (int mi = 0; mi < 4; mi++) {
#pragma unroll
        for (int d = 0; d < 2; d++) {
            const long row = rowBase + wm * 64 + mi * 16 + g + d * 8;
#pragma unroll
            for (int ni = 0; ni < 4; ni++) {
                const int col = colBase + wn * 32 + ni * 8 + 2 * t;
                float v0 = acc[mi][ni][2 * d];
                float v1 = acc[mi][ni][2 * d + 1];
                if (EPI == 3) {
                    v0 += bias[col]; v1 += bias[col + 1];
                    const float* murow  = extra + row * 256;
                    const float* epsrow = aux + row * 256;
                    v0 = fmaf(epsrow[col],     expf(0.5f * v0), murow[col]);
                    v1 = fmaf(epsrow[col + 1], expf(0.5f * v1), murow[col + 1]);
                } else if (EPI == 2) {
                    v0 += extra[row * 256 + col]; v1 += extra[row * 256 + col + 1];
                    v0 = fmaxf(v0, 0.f); v1 = fmaxf(v1, 0.f);
                } else {
                    v0 += bias[col]; v1 += bias[col + 1];
                    if (EPI == 1) { v0 = fmaxf(v0, 0.f); v1 = fmaxf(v1, 0.f); }
                }
                if (OUTH)
                    Ch[row * 128 + (col >> 1)] = __floats2half2_rn(v0, v1);
                else
                    *reinterpret_cast<float2*>(&Cf[row * 256 + col]) = make_float2(v0, v1);
            }
        }
    }
}

// ---------------------------------------------------------------------------
// Fused oth -> (k, v), fp16. Per CTA: 128 agent rows, 512 thr, 2 CTA/SM.
// smem words: OTH [32][128][4] (kp-packed oth), 3 B stages [16][128], A1 [4][128][4]
// ---------------------------------------------------------------------------
#define F_OTH 0
#define F_STG 16384
#define F_A1  22528
#define FSMEM_BYTES 98304

__global__ void __launch_bounds__(512, 2)
fused_okv(const __half2* __restrict__ xh,
          const __half2* __restrict__ Wothp, const float* __restrict__ both,
          const __half2* __restrict__ Wkp,   const float* __restrict__ bk_,
          const __half2* __restrict__ Wvp,
          const float* __restrict__ sev,
          __half2* __restrict__ kb, __half2* __restrict__ vb)
{
    extern __shared__ char sm[];
    unsigned* smw = (unsigned*)sm;
    const uint32_t sb = smem_u32(sm);
    const int tid  = threadIdx.x;
    const int lane = tid & 31;
    const int wid  = tid >> 5;
    const int wm   = wid >> 2;   // 0..3
    const int wn   = wid & 3;    // 0..3
    const int g    = lane >> 2;
    const int t    = lane & 3;
    const long rowBase = (long)blockIdx.x * 128;

    // ---- A1: agents tile (plain loads; 8B-aligned source) ----
    for (int it = tid; it < 2048; it += 512) {
        const int m = it >> 4, w = it & 15;
        unsigned val = 0;
        if (w < 14) {
            long row = rowBase + m;
            int bb = (int)(row / NOTH);
            int nn = (int)(row - (long)bb * NOTH);
            val = *reinterpret_cast<const unsigned*>(&xh[(long)bb * XWP + 18 + nn * 14 + w]);
        }
        smw[F_A1 + (w >> 2) * 512 + m * 4 + (w & 3)] = val;
    }
    // ---- W_oth B tiles (2 col-halves) into stages 0,1 ----
#pragma unroll
    for (int h = 0; h < 2; h++) {
        int idx = tid;
        int bkp = idx >> 5, bn = (idx & 31) << 2;
        int bytes = (bkp < 14) ? 16 : 0;
        const __half2* src = Wothp + (long)(bytes ? bkp : 0) * 256 + h * 128 + bn;
        cpa16(sb + (uint32_t)((F_STG + h * 2048 + bkp * 128 + (bn ^ ((bkp & 3) << 3))) * 4),
              src, bytes);
    }
    asm volatile("cp.async.commit_group;" ::: "memory");
    asm volatile("cp.async.wait_group 0;" ::: "memory");
    __syncthreads();

    // ---- stage 1 compute: oth = relu(agents @ W_oth + b) -> OTH (half2) ----
    for (int h = 0; h < 2; h++) {
        float acc[2][4][4];
#pragma unroll
        for (int mi = 0; mi < 2; mi++)
#pragma unroll
            for (int ni = 0; ni < 4; ni++)
#pragma unroll
                for (int c = 0; c < 4; c++) acc[mi][ni][c] = 0.f;
        const unsigned* As = smw + F_A1;
        const unsigned* Bs = smw + F_STG + h * 2048;
#pragma unroll
        for (int ks = 0; ks < 2; ks++) {
            unsigned a[2][4], b[4][2];
#pragma unroll
            for (int mi = 0; mi < 2; mi++) {
                const int m0 = wm * 32 + mi * 16 + g;
                a[mi][0] = As[(2 * ks) * 512 + m0 * 4 + t];
                a[mi][1] = As[(2 * ks) * 512 + (m0 + 8) * 4 + t];
                a[mi][2] = As[(2 * ks + 1) * 512 + m0 * 4 + t];
                a[mi][3] = As[(2 * ks + 1) * 512 + (m0 + 8) * 4 + t];
            }
#pragma unroll
            for (int ni = 0; ni < 4; ni++) {
                const int nsw = (wn * 32 + ni * 8 + g) ^ (t << 3);
                b[ni][0] = Bs[(ks * 8 + t) * 128 + nsw];
                b[ni][1] = Bs[(ks * 8 + t + 4) * 128 + nsw];
            }
#pragma unroll
            for (int mi = 0; mi < 2; mi++)
#pragma unroll
                for (int ni = 0; ni < 4; ni++)
                    MMA_F16(acc[mi][ni], a[mi], b[ni]);
        }
        // epilogue -> OTH (kp-packed half2 in smem; col pair = one word)
#pragma unroll
        for (int mi = 0; mi < 2; mi++)
#pragma unroll
            for (int d = 0; d < 2; d++) {
                const int rm = wm * 32 + mi * 16 + g + d * 8;
#pragma unroll
                for (int ni = 0; ni < 4; ni++) {
                    const int col = h * 128 + wn * 32 + ni * 8 + 2 * t;
                    float v0 = fmaxf(acc[mi][ni][2 * d]     + both[col],     0.f);
                    float v1 = fmaxf(acc[mi][ni][2 * d + 1] + both[col + 1], 0.f);
                    __half2 hv = __floats2half2_rn(v0, v1);
                    const int kp = col >> 1;
                    smw[F_OTH + (kp >> 2) * 512 + rm * 4 + (kp & 3)] =
                        *reinterpret_cast<unsigned*>(&hv);
                }
            }
    }
    __syncthreads();

    // ---- stage 2: 4 chunks {k-lo, k-hi, v-lo, v-hi}, Kp=128, 8 tiles ----
    for (int cc = 0; cc < 4; cc++) {
        const __half2* W = (cc < 2) ? Wkp : Wvp;
        const int colOff = (cc & 1) * 128;
        __half2* Co = (cc < 2) ? kb : vb;

        auto issueB = [&](int tt, int s) {
            int bkp = tid >> 5, bn = (tid & 31) << 2;
            cpa16(sb + (uint32_t)((F_STG + s * 2048 + bkp * 128 + (bn ^ ((bkp & 3) << 3))) * 4),
                  W + (long)(tt * 16 + bkp) * 256 + colOff + bn, 16);
        };

        float acc[2][4][4];
#pragma unroll
        for (int mi = 0; mi < 2; mi++)
#pragma unroll
            for (int ni = 0; ni < 4; ni++)
#pragma unroll
                for (int c = 0; c < 4; c++) acc[mi][ni][c] = 0.f;

#pragma unroll
        for (int s = 0; s < 3; s++) {
            issueB(s, s);
            asm volatile("cp.async.commit_group;" ::: "memory");
        }

        for (int tt = 0; tt < 8; tt++) {
            asm volatile("cp.async.wait_group 2;" ::: "memory");
            __syncthreads();
            const unsigned* As = smw + F_OTH;
            const unsigned* Bs = smw + F_STG + (tt % 3) * 2048;
#pragma unroll
            for (int ks = 0; ks < 2; ks++) {
                unsigned a[2][4], b[4][2];
                const int grp = tt * 4 + ks * 2;
#pragma unroll
                for (int mi = 0; mi < 2; mi++) {
                    const int m0 = wm * 32 + mi * 16 + g;
                    a[mi][0] = As[grp * 512 + m0 * 4 + t];
                    a[mi][1] = As[grp * 512 + (m0 + 8) * 4 + t];
                    a[mi][2] = As[(grp + 1) * 512 + m0 * 4 + t];
                    a[mi][3] = As[(grp + 1) * 512 + (m0 + 8) * 4 + t];
                }
#pragma unroll
                for (int ni = 0; ni < 4; ni++) {
                    const int nsw = (wn * 32 + ni * 8 + g) ^ (t << 3);
                    b[ni][0] = Bs[(ks * 8 + t) * 128 + nsw];
                    b[ni][1] = Bs[(ks * 8 + t + 4) * 128 + nsw];
                }
#pragma unroll
                for (int mi = 0; mi < 2; mi++)
#pragma unroll
                    for (int ni = 0; ni < 4; ni++)
                        MMA_F16(acc[mi][ni], a[mi], b[ni]);
            }
            __syncthreads();
            if (tt + 3 < 8) issueB(tt + 3, (tt + 3) % 3);
            asm volatile("cp.async.commit_group;" ::: "memory");
        }

#pragma unroll
        for (int mi = 0; mi < 2; mi++)
#pragma unroll
            for (int d = 0; d < 2; d++) {
                const long row = rowBase + wm * 32 + mi * 16 + g + d * 8;
                const float* sv = (cc >= 2) ? (sev + (row / NOTH) * 256) : nullptr;
#pragma unroll
                for (int ni = 0; ni < 4; ni++) {
                    const int col = colOff + wn * 32 + ni * 8 + 2 * t;
                    float v0 = acc[mi][ni][2 * d];
                    float v1 = acc[mi][ni][2 * d + 1];
                    if (cc < 2) { v0 += bk_[col]; v1 += bk_[col + 1]; }
                    else        { v0 += sv[col];  v1 += sv[col + 1]; }
                    v0 = fmaxf(v0, 0.f); v1 = fmaxf(v1, 0.f);
                    Co[row * 128 + (col >> 1)] = __floats2half2_rn(v0, v1);
                }
            }
    }
}

// ---------------------------------------------------------------------------
// Packing kernels
// ---------------------------------------------------------------------------
__global__ void packW(const float* __restrict__ in, __half2* __restrict__ out, int n /*=Kp*256*/)
{
    int i = blockIdx.x * blockDim.x + threadIdx.x;
    if (i < n) {
        int kp = i >> 8, c = i & 255;
        out[i] = __floats2half2_rn(in[(2 * kp) * 256 + c], in[(2 * kp + 1) * 256 + c]);
    }
}
__global__ void packX(const float2* __restrict__ in, __half2* __restrict__ out, int n)
{
    int i = blockIdx.x * blockDim.x + threadIdx.x;
    if (i < n) {
        float2 f = in[i];
        out[i] = __floats2half2_rn(f.x, f.y);
    }
}

// ---------------------------------------------------------------------------
// Attention: scores = q.k/16 -> softmax(19) -> h = att @ v (half2 I/O)
// ---------------------------------------------------------------------------
__global__ void __launch_bounds__(256)
att_kernel(const float* __restrict__ q,
           const __half2* __restrict__ k2,
           const __half2* __restrict__ v2,
           __half2* __restrict__ h2,
           float* __restrict__ att_out)
{
    const int b   = blockIdx.x;
    const int tid = threadIdx.x;
    const int wid = tid >> 5;
    const int lane = tid & 31;

    __shared__ float qs[HDIM];
    __shared__ float sc[32];

    qs[tid] = q[(long)b * HDIM + tid];
    __syncthreads();

    for (int n = wid; n < NOTH; n += 8) {
        const __half2* kp = k2 + ((long)b * NOTH + n) * 128;
        float p = 0.f;
#pragma unroll
        for (int j = 0; j < 4; j++) {
            const int w = lane + 32 * j;
            float2 f = __half22float2(kp[w]);
            p = fmaf(qs[2 * w], f.x, p);
            p = fmaf(qs[2 * w + 1], f.y, p);
        }
#pragma unroll
        for (int off = 16; off > 0; off >>= 1)
            p += __shfl_xor_sync(0xffffffffu, p, off);
        if (lane == 0) sc[n] = p * 0.0625f;
    }
    __syncthreads();

    if (wid == 0) {
        float s = (lane < NOTH) ? sc[lane] : -INFINITY;
        float m = s;
#pragma unroll
        for (int off = 16; off > 0; off >>= 1)
            m = fmaxf(m, __shfl_xor_sync(0xffffffffu, m, off));
        float e = (lane < NOTH) ? expf(s - m) : 0.f;
        float sum = e;
#pragma unroll
        for (int off = 16; off > 0; off >>= 1)
            sum += __shfl_xor_sync(0xffffffffu, sum, off);
        const float a = e / sum;
        if (lane < NOTH) {
            sc[lane] = a;
            att_out[(long)b * NOTH + lane] = a;
        }
    }
    __syncthreads();

    if (tid < 128) {
        const __half2* vp = v2 + (long)b * NOTH * 128 + tid;
        float ax = 0.f, ay = 0.f;
#pragma unroll
        for (int n = 0; n < NOTH; n++) {
            float2 f = __half22float2(vp[(long)n * 128]);
            ax = fmaf(sc[n], f.x, ax);
            ay = fmaf(sc[n], f.y, ay);
        }
        h2[(long)b * 128 + tid] = __floats2half2_rn(ax, ay);
    }
}

// ---------------------------------------------------------------------------
// Launch
// ---------------------------------------------------------------------------
extern "C" void kernel_launch(void* const* d_in, const int* in_sizes, int n_in,
                              void* d_out, int out_size)
{
    const float* x      = (const float*)d_in[0];
    const float* eps    = (const float*)d_in[1];
    const float* W_mu   = (const float*)d_in[2];
    const float* b_mu   = (const float*)d_in[3];
    const float* W_var  = (const float*)d_in[4];
    const float* b_var  = (const float*)d_in[5];
    const float* W_self = (const float*)d_in[6];
    const float* b_self = (const float*)d_in[7];
    const float* W_oth  = (const float*)d_in[8];
    const float* b_oth  = (const float*)d_in[9];
    const float* W_q    = (const float*)d_in[10];
    const float* b_q    = (const float*)d_in[11];
    const float* W_k    = (const float*)d_in[12];
    const float* b_k    = (const float*)d_in[13];
    const float* W_v    = (const float*)d_in[14];
    const float* b_v    = (const float*)d_in[15];
    const float* W_a    = (const float*)d_in[16];
    const float* b_a    = (const float*)d_in[17];

    float* out_main = (float*)d_out;
    float* out_att  = (float*)d_out + (long)BATCH * HDIM;

    float *mu, *q, *sev, *spa;
    __half2 *zh, *selfh, *hh, *kh, *vh, *xh, *wp;
    cudaGetSymbolAddress((void**)&mu,    g_mu);
    cudaGetSymbolAddress((void**)&q,     g_q);
    cudaGetSymbolAddress((void**)&sev,   g_sev);
    cudaGetSymbolAddress((void**)&spa,   g_spa);
    cudaGetSymbolAddress((void**)&zh,    g_zh);
    cudaGetSymbolAddress((void**)&selfh, g_selfh);
    cudaGetSymbolAddress((void**)&hh,    g_hh);
    cudaGetSymbolAddress((void**)&kh,    g_kh);
    cudaGetSymbolAddress((void**)&vh,    g_vh);
    cudaGetSymbolAddress((void**)&xh,    g_xh);
    cudaGetSymbolAddress((void**)&wp,    g_wp);

    cudaFuncSetAttribute(hgemm<0,0>, cudaFuncAttributeMaxDynamicSharedMemorySize, GSMEM_BYTES);
    cudaFuncSetAttribute(hgemm<1,0>, cudaFuncAttributeMaxDynamicSharedMemorySize, GSMEM_BYTES);
    cudaFuncSetAttribute(hgemm<1,1>, cudaFuncAttributeMaxDynamicSharedMemorySize, GSMEM_BYTES);
    cudaFuncSetAttribute(hgemm<2,0>, cudaFuncAttributeMaxDynamicSharedMemorySize, GSMEM_BYTES);
    cudaFuncSetAttribute(hgemm<3,1>, cudaFuncAttributeMaxDynamicSharedMemorySize, GSMEM_BYTES);
    cudaFuncSetAttribute(fused_okv,  cudaFuncAttributeMaxDynamicSharedMemorySize, FSMEM_BYTES);

    // Pack operands to half2 (kp-paired)
    {
        auto pw = [&](const float* src, long off, int Kp) {
            int n = Kp * 256;
            packW<<<(n + 255) / 256, 256>>>(src, wp + off, n);
        };
        pw(W_mu,   WT2_MU,   284);
        pw(W_var,  WT2_VAR,  284);
        pw(W_self, WT2_SELF, 18);
        pw(W_oth,  WT2_OTH,  14);
        pw(W_q,    WT2_Q,    128);
        pw(W_k,    WT2_K,    128);
        pw(W_v,    WT2_V,    256);
        pw(W_a,    WT2_A,    256);
        int nx = BATCH * XWP;
        packX<<<(nx + 255) / 256, 256>>>((const float2*)x, xh, nx);
    }

    const dim3 blk(256);
    const dim3 gB(2, BATCH / 128);

    // mu = x @ W_mu + b_mu (fp32 out)
    hgemm<0,0><<<gB, blk, GSMEM_BYTES>>>(xh, XWP, wp + WT2_MU, b_mu, nullptr, nullptr, mu, nullptr, 284);
    // z = eps * exp(0.5*(x@W_var+b_var)) + mu  (half out)
    hgemm<3,1><<<gB, blk, GSMEM_BYTES>>>(xh, XWP, wp + WT2_VAR, b_var, mu, eps, nullptr, zh, 284);
    // self_em = relu(x[:, :36] @ W_self + b) (half out)
    hgemm<1,1><<<gB, blk, GSMEM_BYTES>>>(xh, XWP, wp + WT2_SELF, b_self, nullptr, nullptr, nullptr, selfh, 18);
    // sev = self_em @ W_v[256:] + b_v (fp32 out)
    hgemm<0,0><<<gB, blk, GSMEM_BYTES>>>(selfh, 128, wp + WT2_V + 128 * 256, b_v, nullptr, nullptr, sev, nullptr, 128);
    // fused: oth (smem) -> k, v (half out)
    fused_okv<<<MROWS / 128, 512, FSMEM_BYTES>>>(xh, wp + WT2_OTH, b_oth,
                                                 wp + WT2_K, b_k, wp + WT2_V,
                                                 sev, kh, vh);
    // q = relu(z @ W_q + b) (fp32 out; feeds att only)
    hgemm<1,0><<<gB, blk, GSMEM_BYTES>>>(zh, 128, wp + WT2_Q, b_q, nullptr, nullptr, q, nullptr, 128);
    // attention
    att_kernel<<<BATCH, 256>>>(q, kh, vh, hh, out_att);
    // spa = self_em @ W_a[256:] + b_a (fp32 out)
    hgemm<0,0><<<gB, blk, GSMEM_BYTES>>>(selfh, 128, wp + WT2_A + 128 * 256, b_a, nullptr, nullptr, spa, nullptr, 128);
    // out = relu(h @ W_a[:256] + spa) (fp32 out)
    hgemm<2,0><<<gB, blk, GSMEM_BYTES>>>(hh, 128, wp + WT2_A, nullptr, spa, nullptr, out_main, nullptr, 128);
}

// round 12
// speedup vs baseline: 6.5950x; 1.0697x over previous
#include <cuda_runtime.h>
#include <cuda_fp16.h>
#include <stdint.h>
#include <math.h>

// Problem constants
#define BATCH   16384
#define OBS     568
#define HDIM    256
#define SELFD   36
#define OTHD    28
#define NOTH    19
#define MROWS   (BATCH*NOTH)
#define XWP     284          // OBS/2 half2 words per x row

// ---------------------------------------------------------------------------
// Scratch (device globals; allocation is forbidden)
// ---------------------------------------------------------------------------
__device__ float   g_mu  [BATCH*HDIM];
__device__ float   g_q   [BATCH*HDIM];
__device__ float   g_sev [BATCH*HDIM];
__device__ float   g_spa [BATCH*HDIM];
__device__ __half2 g_zh  [BATCH*128];
__device__ __half2 g_selfh[BATCH*128];
__device__ __half2 g_hh  [BATCH*128];
__device__ __half2 g_kh  [MROWS*128];
__device__ __half2 g_vh  [MROWS*128];
__device__ __half2 g_xh  [BATCH*XWP];
// Packed weights [Kp][256] half2 (lo = even k, hi = odd k). Word offsets:
#define WT2_MU   0
#define WT2_VAR  72704
#define WT2_SELF 145408
#define WT2_OTH  150016
#define WT2_Q    153600
#define WT2_K    186368
#define WT2_V    219136
#define WT2_A    284672
#define WT2_END  350208
__device__ __half2 g_wp[WT2_END];

// ---------------------------------------------------------------------------
// Helpers
// ---------------------------------------------------------------------------
__device__ __forceinline__ uint32_t smem_u32(const void* p) {
    uint32_t a;
    asm("{ .reg .u64 t; cvta.to.shared.u64 t, %1; cvt.u32.u64 %0, t; }"
        : "=r"(a) : "l"(p));
    return a;
}
__device__ __forceinline__ void cpa16(uint32_t dst, const void* src, int bytes) {
    asm volatile("cp.async.cg.shared.global [%0], [%1], 16, %2;"
                 :: "r"(dst), "l"(src), "r"(bytes) : "memory");
}
#define CP_COMMIT() asm volatile("cp.async.commit_group;" ::: "memory")
#define CP_WAIT2()  asm volatile("cp.async.wait_group 2;" ::: "memory")
#define MMA_F16(acc, a, b) \
    asm volatile( \
        "mma.sync.aligned.m16n8k16.row.col.f32.f16.f16.f32 " \
        "{%0,%1,%2,%3},{%4,%5,%6,%7},{%8,%9},{%0,%1,%2,%3};" \
        : "+f"((acc)[0]), "+f"((acc)[1]), "+f"((acc)[2]), "+f"((acc)[3]) \
        : "r"((a)[0]), "r"((a)[1]), "r"((a)[2]), "r"((a)[3]), \
          "r"((b)[0]), "r"((b)[1]))
#define LDSM_X4(r0, r1, r2, r3, addr) \
    asm volatile("ldmatrix.sync.aligned.m8n8.x4.shared.b16 {%0,%1,%2,%3}, [%4];" \
                 : "=r"(r0), "=r"(r1), "=r"(r2), "=r"(r3) : "r"(addr))

// A smem layout (interleaved for ldmatrix): row m, kp-chunk c (16B = 4 words):
//   p = m>>1, hs = m&1, line = c>>2 (for OTH), slot = (hs*4 + (c&3)) ^ (p&7)
//   word = p*prowWords + line*32 + slot*4 + win
// ldmatrix phase (8 rows, fixed c) hits 8 distinct 16B slots -> conflict-free.

// ---------------------------------------------------------------------------
// FP16 mma.sync GEMM, cp.async 4-stage pipeline, ldmatrix A fragments.
// C[M,256] = epi(A[M,2*Kp] @ W[2*Kp,256]); operands half2 kp-packed.
// BM=128, BN=128, BKp=16 (K=32), 256 threads (8 warps 2x4), warp tile 64x32.
// EPI : 0 = +bias; 1 = relu(+bias); 2 = relu(+extra[row*256+col]);
//       3 = z-fusion: lv=acc+bias; C = fma(aux, exp(0.5*lv), extra) per elem
// OUTH: 1 = write half2-packed Ch[row*128+col/2]; 0 = write fp32 Cf.
// ---------------------------------------------------------------------------
#define GSMEM_BYTES 65536   // 4 stages x (A 8KB + B 8KB)

template<int EPI, int OUTH>
__global__ void __launch_bounds__(256, 2)
hgemm(const __half2* __restrict__ A, int lda,
      const __half2* __restrict__ W,
      const float* __restrict__ bias,
      const float* __restrict__ extra,
      const float* __restrict__ aux,
      float* __restrict__ Cf, __half2* __restrict__ Ch,
      int Kp)
{
    extern __shared__ char sm[];
    const uint32_t sb = smem_u32(sm);
    const int tid  = threadIdx.x;
    const int lane = tid & 31;
    const int wid  = tid >> 5;
    const int wm   = wid >> 2;
    const int wn   = wid & 3;
    const int g    = lane >> 2;
    const int t    = lane & 3;

    const long rowBase = (long)blockIdx.y * 128;
    const int  colBase = blockIdx.x * 128;

    // A producer: 2 chunks of 16B; chunk j = (row am, kp-chunk ac)
    int am[2], ac[2]; long abase[2]; uint32_t adst[2];
#pragma unroll
    for (int j = 0; j < 2; j++) {
        int idx = tid + j * 256;     // 0..511
        am[j] = idx >> 2;            // 0..127
        ac[j] = idx & 3;             // 0..3
        abase[j] = (rowBase + am[j]) * (long)lda;
        int p = am[j] >> 1, hs = am[j] & 1;
        adst[j] = (uint32_t)((p * 32 + (((hs * 4) + ac[j]) ^ (p & 7)) * 4) * 4);
    }

    auto issue = [&](int tt, int s) {
        const int ktp = tt << 4;
        const uint32_t sA = sb + (uint32_t)s * 16384u;
        const uint32_t sB = sA + 8192u;
#pragma unroll
        for (int j = 0; j < 2; j++) {
            int kg  = ktp + ac[j] * 4;
            int rem = Kp - kg;
            int bytes = (rem <= 0) ? 0 : ((rem >= 4) ? 16 : rem * 4);
            cpa16(sA + adst[j], A + abase[j] + (bytes ? kg : 0), bytes);
        }
#pragma unroll
        for (int j = 0; j < 2; j++) {
            int idx = tid + j * 256;
            int bkp = idx >> 5;           // 0..15
            int bn  = (idx & 31) << 2;    // 0..124
            int kg  = ktp + bkp;
            int bytes = (kg < Kp) ? 16 : 0;
            cpa16(sB + (uint32_t)((bkp * 128 + (bn ^ ((bkp & 3) << 3))) * 4),
                  W + (long)(bytes ? kg : 0) * 256 + colBase + bn, bytes);
        }
    };

    // ldmatrix lane geometry
    const int lm = ((lane >> 3) & 1) * 8 + (lane & 7);  // row offset in 16
    const int lc = lane >> 4;                           // chunk offset 0/1
    int apb[4], ahs4[4], ap7[4];
#pragma unroll
    for (int mi = 0; mi < 4; mi++) {
        int m = wm * 64 + mi * 16 + lm;
        apb[mi]  = (m >> 1) * 32;
        ahs4[mi] = (m & 1) * 4;
        ap7[mi]  = (m >> 1) & 7;
    }

    float acc[4][4][4];
#pragma unroll
    for (int mi = 0; mi < 4; mi++)
#pragma unroll
        for (int ni = 0; ni < 4; ni++)
#pragma unroll
            for (int c = 0; c < 4; c++) acc[mi][ni][c] = 0.f;

    const int nt = (Kp + 15) >> 4;
#pragma unroll
    for (int s = 0; s < 3; s++) {
        if (s < nt) issue(s, s);
        CP_COMMIT();
    }

    for (int tt = 0; tt < nt; tt++) {
        CP_WAIT2();
        __syncthreads();
        const int tn = tt + 3;
        if (tn < nt) issue(tn, tn & 3);
        CP_COMMIT();

        const uint32_t sA = sb + (uint32_t)(tt & 3) * 16384u;
        const unsigned* Bs = (const unsigned*)(sm + (tt & 3) * 16384 + 8192);
#pragma unroll
        for (int ks = 0; ks < 2; ks++) {
            unsigned a[4][4], b[4][2];
            const int c = 2 * ks + lc;
#pragma unroll
            for (int mi = 0; mi < 4; mi++) {
                uint32_t addr = sA + (uint32_t)((apb[mi] + ((ahs4[mi] + c) ^ ap7[mi]) * 4) * 4);
                LDSM_X4(a[mi][0], a[mi][1], a[mi][2], a[mi][3], addr);
            }
#pragma unroll
            for (int ni = 0; ni < 4; ni++) {
                const int nsw = (wn * 32 + ni * 8 + g) ^ (t << 3);
                b[ni][0] = Bs[(ks * 8 + t) * 128 + nsw];
                b[ni][1] = Bs[(ks * 8 + t + 4) * 128 + nsw];
            }
#pragma unroll
            for (int mi = 0; mi < 4; mi++)
#pragma unroll
                for (int ni = 0; ni < 4; ni++)
                    MMA_F16(acc[mi][ni], a[mi], b[ni]);
        }
    }

#pragma unroll
    for (int mi = 0; mi < 4; mi++) {
#pragma unroll
        for (int d = 0; d < 2; d++) {
            const long row = rowBase + wm * 64 + mi * 16 + g + d * 8;
#pragma unroll
            for (int ni = 0; ni < 4; ni++) {
                const int col = colBase + wn * 32 + ni * 8 + 2 * t;
                float v0 = acc[mi][ni][2 * d];
                float v1 = acc[mi][ni][2 * d + 1];
                if (EPI == 3) {
                    v0 += bias[col]; v1 += bias[col + 1];
                    const float* murow  = extra + row * 256;
                    const float* epsrow = aux + row * 256;
                    v0 = fmaf(epsrow[col],     expf(0.5f * v0), murow[col]);
                    v1 = fmaf(epsrow[col + 1], expf(0.5f * v1), murow[col + 1]);
                } else if (EPI == 2) {
                    v0 += extra[row * 256 + col]; v1 += extra[row * 256 + col + 1];
                    v0 = fmaxf(v0, 0.f); v1 = fmaxf(v1, 0.f);
                } else {
                    v0 += bias[col]; v1 += bias[col + 1];
                    if (EPI == 1) { v0 = fmaxf(v0, 0.f); v1 = fmaxf(v1, 0.f); }
                }
                if (OUTH)
                    Ch[row * 128 + (col >> 1)] = __floats2half2_rn(v0, v1);
                else
                    *reinterpret_cast<float2*>(&Cf[row * 256 + col]) = make_float2(v0, v1);
            }
        }
    }
}

// ---------------------------------------------------------------------------
// Fused oth -> (k, v), fp16 + ldmatrix. Per CTA: 128 agent rows, 512 thr, 2/SM.
// smem words: OTH 16384 (interleaved ldmatrix layout, prow=256 words),
//             A1 2048 (prow=32), 4 B stages x 2048.
// ---------------------------------------------------------------------------
#define F_OTH 0
#define F_A1  16384
#define F_STG 18432
#define FSMEM_BYTES 106496

__global__ void __launch_bounds__(512, 2)
fused_okv(const __half2* __restrict__ xh,
          const __half2* __restrict__ Wothp, const float* __restrict__ both,
          const __half2* __restrict__ Wkp,   const float* __restrict__ bk_,
          const __half2* __restrict__ Wvp,
          const float* __restrict__ sev,
          __half2* __restrict__ kb, __half2* __restrict__ vb)
{
    extern __shared__ char sm[];
    unsigned* smw = (unsigned*)sm;
    const uint32_t sb = smem_u32(sm);
    const int tid  = threadIdx.x;
    const int lane = tid & 31;
    const int wid  = tid >> 5;
    const int wm   = wid >> 2;   // 0..3
    const int wn   = wid & 3;    // 0..3
    const int g    = lane >> 2;
    const int t    = lane & 3;
    const long rowBase = (long)blockIdx.x * 128;

    const int lm = ((lane >> 3) & 1) * 8 + (lane & 7);
    const int lc = lane >> 4;
    // ldmatrix geometry for warp tile 32x32 (mi<2), rows m0 = wm*32+mi*16
    int apbO[2], apbA[2], ahs4[2], ap7[2];
#pragma unroll
    for (int mi = 0; mi < 2; mi++) {
        int m = wm * 32 + mi * 16 + lm;
        apbO[mi] = (m >> 1) * 256;   // OTH prow = 256 words
        apbA[mi] = (m >> 1) * 32;    // A1 prow = 32 words
        ahs4[mi] = (m & 1) * 4;
        ap7[mi]  = (m >> 1) & 7;
    }

    // ---- A1: agents tile (plain word loads into interleaved layout) ----
    for (int it = tid; it < 2048; it += 512) {
        const int m = it >> 4, w = it & 15;
        unsigned val = 0;
        if (w < 14) {
            long row = rowBase + m;
            int bb = (int)(row / NOTH);
            int nn = (int)(row - (long)bb * NOTH);
            val = *reinterpret_cast<const unsigned*>(&xh[(long)bb * XWP + 18 + nn * 14 + w]);
        }
        const int p = m >> 1, hs = m & 1, c = w >> 2, win = w & 3;
        smw[F_A1 + p * 32 + ((hs * 4 + c) ^ (p & 7)) * 4 + win] = val;
    }
    // ---- W_oth B tiles (2 col-halves) into stages 0,1 ----
#pragma unroll
    for (int h = 0; h < 2; h++) {
        int bkp = tid >> 5, bn = (tid & 31) << 2;
        int bytes = (bkp < 14) ? 16 : 0;
        const __half2* src = Wothp + (long)(bytes ? bkp : 0) * 256 + h * 128 + bn;
        cpa16(sb + (uint32_t)((F_STG + h * 2048 + bkp * 128 + (bn ^ ((bkp & 3) << 3))) * 4),
              src, bytes);
    }
    CP_COMMIT();
    asm volatile("cp.async.wait_group 0;" ::: "memory");
    __syncthreads();

    // ---- stage 1: oth = relu(agents @ W_oth + b) -> OTH (half2, interleaved) ----
    for (int h = 0; h < 2; h++) {
        float acc[2][4][4];
#pragma unroll
        for (int mi = 0; mi < 2; mi++)
#pragma unroll
            for (int ni = 0; ni < 4; ni++)
#pragma unroll
                for (int c = 0; c < 4; c++) acc[mi][ni][c] = 0.f;
        const unsigned* Bs = smw + F_STG + h * 2048;
#pragma unroll
        for (int ks = 0; ks < 2; ks++) {
            unsigned a[2][4], b[4][2];
            const int c = 2 * ks + lc;
#pragma unroll
            for (int mi = 0; mi < 2; mi++) {
                uint32_t addr = sb + (uint32_t)((F_A1 + apbA[mi] + ((ahs4[mi] + c) ^ ap7[mi]) * 4) * 4);
                LDSM_X4(a[mi][0], a[mi][1], a[mi][2], a[mi][3], addr);
            }
#pragma unroll
            for (int ni = 0; ni < 4; ni++) {
                const int nsw = (wn * 32 + ni * 8 + g) ^ (t << 3);
                b[ni][0] = Bs[(ks * 8 + t) * 128 + nsw];
                b[ni][1] = Bs[(ks * 8 + t + 4) * 128 + nsw];
            }
#pragma unroll
            for (int mi = 0; mi < 2; mi++)
#pragma unroll
                for (int ni = 0; ni < 4; ni++)
                    MMA_F16(acc[mi][ni], a[mi], b[ni]);
        }
        // epilogue -> OTH (interleaved: chunk c = h*16 + wn*4 + ni, win = t)
#pragma unroll
        for (int mi = 0; mi < 2; mi++)
#pragma unroll
            for (int d = 0; d < 2; d++) {
                const int rm = wm * 32 + mi * 16 + g + d * 8;
                const int p = rm >> 1, hs = rm & 1;
#pragma unroll
                for (int ni = 0; ni < 4; ni++) {
                    const int col = h * 128 + wn * 32 + ni * 8 + 2 * t;
                    float v0 = fmaxf(acc[mi][ni][2 * d]     + both[col],     0.f);
                    float v1 = fmaxf(acc[mi][ni][2 * d + 1] + both[col + 1], 0.f);
                    __half2 hv = __floats2half2_rn(v0, v1);
                    const int line = h * 4 + wn;             // c>>2
                    smw[F_OTH + p * 256 + line * 32 + ((hs * 4 + ni) ^ (p & 7)) * 4 + t] =
                        *reinterpret_cast<unsigned*>(&hv);
                }
            }
    }
    __syncthreads();

    // ---- stage 2: 4 chunks {k-lo, k-hi, v-lo, v-hi}, Kp=128, 8 tiles, 4-stage ----
    for (int cc = 0; cc < 4; cc++) {
        const __half2* W = (cc < 2) ? Wkp : Wvp;
        const int colOff = (cc & 1) * 128;
        __half2* Co = (cc < 2) ? kb : vb;

        auto issueB = [&](int tt, int s) {
            int bkp = tid >> 5, bn = (tid & 31) << 2;
            cpa16(sb + (uint32_t)((F_STG + s * 2048 + bkp * 128 + (bn ^ ((bkp & 3) << 3))) * 4),
                  W + (long)(tt * 16 + bkp) * 256 + colOff + bn, 16);
        };

        float acc[2][4][4];
#pragma unroll
        for (int mi = 0; mi < 2; mi++)
#pragma unroll
            for (int ni = 0; ni < 4; ni++)
#pragma unroll
                for (int c = 0; c < 4; c++) acc[mi][ni][c] = 0.f;

#pragma unroll
        for (int s = 0; s < 3; s++) {
            issueB(s, s);
            CP_COMMIT();
        }

        for (int tt = 0; tt < 8; tt++) {
            CP_WAIT2();
            __syncthreads();
            if (tt + 3 < 8) issueB(tt + 3, (tt + 3) & 3);
            CP_COMMIT();

            const unsigned* Bs = smw + F_STG + (tt & 3) * 2048;
#pragma unroll
            for (int ks = 0; ks < 2; ks++) {
                unsigned a[2][4], b[4][2];
                const int c3 = 2 * ks + lc;            // c&3
#pragma unroll
                for (int mi = 0; mi < 2; mi++) {
                    uint32_t addr = sb + (uint32_t)((F_OTH + apbO[mi] + tt * 32
                                     + ((ahs4[mi] + c3) ^ ap7[mi]) * 4) * 4);
                    LDSM_X4(a[mi][0], a[mi][1], a[mi][2], a[mi][3], addr);
                }
#pragma unroll
                for (int ni = 0; ni < 4; ni++) {
                    const int nsw = (wn * 32 + ni * 8 + g) ^ (t << 3);
                    b[ni][0] = Bs[(ks * 8 + t) * 128 + nsw];
                    b[ni][1] = Bs[(ks * 8 + t + 4) * 128 + nsw];
                }
#pragma unroll
                for (int mi = 0; mi < 2; mi++)
#pragma unroll
                    for (int ni = 0; ni < 4; ni++)
                        MMA_F16(acc[mi][ni], a[mi], b[ni]);
            }
        }

#pragma unroll
        for (int mi = 0; mi < 2; mi++)
#pragma unroll
            for (int d = 0; d < 2; d++) {
                const long row = rowBase + wm * 32 + mi * 16 + g + d * 8;
                const float* sv = (cc >= 2) ? (sev + (row / NOTH) * 256) : nullptr;
#pragma unroll
                for (int ni = 0; ni < 4; ni++) {
                    const int col = colOff + wn * 32 + ni * 8 + 2 * t;
                    float v0 = acc[mi][ni][2 * d];
                    float v1 = acc[mi][ni][2 * d + 1];
                    if (cc < 2) { v0 += bk_[col]; v1 += bk_[col + 1]; }
                    else        { v0 += sv[col];  v1 += sv[col + 1]; }
                    v0 = fmaxf(v0, 0.f); v1 = fmaxf(v1, 0.f);
                    Co[row * 128 + (col >> 1)] = __floats2half2_rn(v0, v1);
                }
            }
    }
}

// ---------------------------------------------------------------------------
// Packing kernels
// ---------------------------------------------------------------------------
__global__ void packAllW(const float* __restrict__ Wmu, const float* __restrict__ Wvar,
                         const float* __restrict__ Wself, const float* __restrict__ Woth,
                         const float* __restrict__ Wq, const float* __restrict__ Wk,
                         const float* __restrict__ Wv, const float* __restrict__ Wa,
                         __half2* __restrict__ out)
{
    int i = blockIdx.x * blockDim.x + threadIdx.x;
    if (i >= WT2_END) return;
    const float* src; int base;
    if      (i < WT2_VAR)  { src = Wmu;   base = WT2_MU;   }
    else if (i < WT2_SELF) { src = Wvar;  base = WT2_VAR;  }
    else if (i < WT2_OTH)  { src = Wself; base = WT2_SELF; }
    else if (i < WT2_Q)    { src = Woth;  base = WT2_OTH;  }
    else if (i < WT2_K)    { src = Wq;    base = WT2_Q;    }
    else if (i < WT2_V)    { src = Wk;    base = WT2_K;    }
    else if (i < WT2_A)    { src = Wv;    base = WT2_V;    }
    else                   { src = Wa;    base = WT2_A;    }
    int r = i - base, kp = r >> 8, c = r & 255;
    out[i] = __floats2half2_rn(src[(2 * kp) * 256 + c], src[(2 * kp + 1) * 256 + c]);
}
__global__ void packX(const float2* __restrict__ in, __half2* __restrict__ out, int n)
{
    int i = blockIdx.x * blockDim.x + threadIdx.x;
    if (i < n) {
        float2 f = in[i];
        out[i] = __floats2half2_rn(f.x, f.y);
    }
}

// ---------------------------------------------------------------------------
// Attention: scores = q.k/16 -> softmax(19) -> h = att @ v (half2 I/O)
// ---------------------------------------------------------------------------
__global__ void __launch_bounds__(256)
att_kernel(const float* __restrict__ q,
           const __half2* __restrict__ k2,
           const __half2* __restrict__ v2,
           __half2* __restrict__ h2,
           float* __restrict__ att_out)
{
    const int b   = blockIdx.x;
    const int tid = threadIdx.x;
    const int wid = tid >> 5;
    const int lane = tid & 31;

    __shared__ float qs[HDIM];
    __shared__ float sc[32];

    qs[tid] = q[(long)b * HDIM + tid];
    __syncthreads();

    for (int n = wid; n < NOTH; n += 8) {
        const __half2* kp = k2 + ((long)b * NOTH + n) * 128;
        float p = 0.f;
#pragma unroll
        for (int j = 0; j < 4; j++) {
            const int w = lane + 32 * j;
            float2 f = __half22float2(kp[w]);
            p = fmaf(qs[2 * w], f.x, p);
            p = fmaf(qs[2 * w + 1], f.y, p);
        }
#pragma unroll
        for (int off = 16; off > 0; off >>= 1)
            p += __shfl_xor_sync(0xffffffffu, p, off);
        if (lane == 0) sc[n] = p * 0.0625f;
    }
    __syncthreads();

    if (wid == 0) {
        float s = (lane < NOTH) ? sc[lane] : -INFINITY;
        float m = s;
#pragma unroll
        for (int off = 16; off > 0; off >>= 1)
            m = fmaxf(m, __shfl_xor_sync(0xffffffffu, m, off));
        float e = (lane < NOTH) ? expf(s - m) : 0.f;
        float sum = e;
#pragma unroll
        for (int off = 16; off > 0; off >>= 1)
            sum += __shfl_xor_sync(0xffffffffu, sum, off);
        const float a = e / sum;
        if (lane < NOTH) {
            sc[lane] = a;
            att_out[(long)b * NOTH + lane] = a;
        }
    }
    __syncthreads();

    if (tid < 128) {
        const __half2* vp = v2 + (long)b * NOTH * 128 + tid;
        float ax = 0.f, ay = 0.f;
#pragma unroll
        for (int n = 0; n < NOTH; n++) {
            float2 f = __half22float2(vp[(long)n * 128]);
            ax = fmaf(sc[n], f.x, ax);
            ay = fmaf(sc[n], f.y, ay);
        }
        h2[(long)b * 128 + tid] = __floats2half2_rn(ax, ay);
    }
}

// ---------------------------------------------------------------------------
// Launch
// ---------------------------------------------------------------------------
extern "C" void kernel_launch(void* const* d_in, const int* in_sizes, int n_in,
                              void* d_out, int out_size)
{
    const float* x      = (const float*)d_in[0];
    const float* eps    = (const float*)d_in[1];
    const float* W_mu   = (const float*)d_in[2];
    const float* b_mu   = (const float*)d_in[3];
    const float* W_var  = (const float*)d_in[4];
    const float* b_var  = (const float*)d_in[5];
    const float* W_self = (const float*)d_in[6];
    const float* b_self = (const float*)d_in[7];
    const float* W_oth  = (const float*)d_in[8];
    const float* b_oth  = (const float*)d_in[9];
    const float* W_q    = (const float*)d_in[10];
    const float* b_q    = (const float*)d_in[11];
    const float* W_k    = (const float*)d_in[12];
    const float* b_k    = (const float*)d_in[13];
    const float* W_v    = (const float*)d_in[14];
    const float* b_v    = (const float*)d_in[15];
    const float* W_a    = (const float*)d_in[16];
    const float* b_a    = (const float*)d_in[17];

    float* out_main = (float*)d_out;
    float* out_att  = (float*)d_out + (long)BATCH * HDIM;

    float *mu, *q, *sev, *spa;
    __half2 *zh, *selfh, *hh, *kh, *vh, *xh, *wp;
    cudaGetSymbolAddress((void**)&mu,    g_mu);
    cudaGetSymbolAddress((void**)&q,     g_q);
    cudaGetSymbolAddress((void**)&sev,   g_sev);
    cudaGetSymbolAddress((void**)&spa,   g_spa);
    cudaGetSymbolAddress((void**)&zh,    g_zh);
    cudaGetSymbolAddress((void**)&selfh, g_selfh);
    cudaGetSymbolAddress((void**)&hh,    g_hh);
    cudaGetSymbolAddress((void**)&kh,    g_kh);
    cudaGetSymbolAddress((void**)&vh,    g_vh);
    cudaGetSymbolAddress((void**)&xh,    g_xh);
    cudaGetSymbolAddress((void**)&wp,    g_wp);

    cudaFuncSetAttribute(hgemm<0,0>, cudaFuncAttributeMaxDynamicSharedMemorySize, GSMEM_BYTES);
    cudaFuncSetAttribute(hgemm<1,0>, cudaFuncAttributeMaxDynamicSharedMemorySize, GSMEM_BYTES);
    cudaFuncSetAttribute(hgemm<1,1>, cudaFuncAttributeMaxDynamicSharedMemorySize, GSMEM_BYTES);
    cudaFuncSetAttribute(hgemm<2,0>, cudaFuncAttributeMaxDynamicSharedMemorySize, GSMEM_BYTES);
    cudaFuncSetAttribute(hgemm<3,1>, cudaFuncAttributeMaxDynamicSharedMemorySize, GSMEM_BYTES);
    cudaFuncSetAttribute(fused_okv,  cudaFuncAttributeMaxDynamicSharedMemorySize, FSMEM_BYTES);

    // Pack operands to half2 (kp-paired)
    packAllW<<<(WT2_END + 255) / 256, 256>>>(W_mu, W_var, W_self, W_oth,
                                             W_q, W_k, W_v, W_a, wp);
    {
        int nx = BATCH * XWP;
        packX<<<(nx + 255) / 256, 256>>>((const float2*)x, xh, nx);
    }

    const dim3 blk(256);
    const dim3 gB(2, BATCH / 128);

    // mu = x @ W_mu + b_mu (fp32 out)
    hgemm<0,0><<<gB, blk, GSMEM_BYTES>>>(xh, XWP, wp + WT2_MU, b_mu, nullptr, nullptr, mu, nullptr, 284);
    // z = eps * exp(0.5*(x@W_var+b_var)) + mu  (half out)
    hgemm<3,1><<<gB, blk, GSMEM_BYTES>>>(xh, XWP, wp + WT2_VAR, b_var, mu, eps, nullptr, zh, 284);
    // self_em = relu(x[:, :36] @ W_self + b) (half out)
    hgemm<1,1><<<gB, blk, GSMEM_BYTES>>>(xh, XWP, wp + WT2_SELF, b_self, nullptr, nullptr, nullptr, selfh, 18);
    // sev = self_em @ W_v[256:] + b_v (fp32 out)
    hgemm<0,0><<<gB, blk, GSMEM_BYTES>>>(selfh, 128, wp + WT2_V + 128 * 256, b_v, nullptr, nullptr, sev, nullptr, 128);
    // fused: oth (smem) -> k, v (half out)
    fused_okv<<<MROWS / 128, 512, FSMEM_BYTES>>>(xh, wp + WT2_OTH, b_oth,
                                                 wp + WT2_K, b_k, wp + WT2_V,
                                                 sev, kh, vh);
    // q = relu(z @ W_q + b) (fp32 out; feeds att only)
    hgemm<1,0><<<gB, blk, GSMEM_BYTES>>>(zh, 128, wp + WT2_Q, b_q, nullptr, nullptr, q, nullptr, 128);
    // attention
    att_kernel<<<BATCH, 256>>>(q, kh, vh, hh, out_att);
    // spa = self_em @ W_a[256:] + b_a (fp32 out)
    hgemm<0,0><<<gB, blk, GSMEM_BYTES>>>(selfh, 128, wp + WT2_A + 128 * 256, b_a, nullptr, nullptr, spa, nullptr, 128);
    // out = relu(h @ W_a[:256] + spa) (fp32 out)
    hgemm<2,0><<<gB, blk, GSMEM_BYTES>>>(hh, 128, wp + WT2_A, nullptr, spa, nullptr, out_main, nullptr, 128);
}

// round 13
// speedup vs baseline: 7.2524x; 1.0997x over previous
#include <cuda_runtime.h>
#include <cuda_fp16.h>
#include <stdint.h>
#include <math.h>

// Problem constants
#define BATCH   16384
#define OBS     568
#define HDIM    256
#define SELFD   36
#define OTHD    28
#define NOTH    19
#define MROWS   (BATCH*NOTH)
#define XWP     284          // OBS/2 half2 words per x row

// ---------------------------------------------------------------------------
// Scratch (device globals; allocation is forbidden)
// ---------------------------------------------------------------------------
__device__ float   g_mu  [BATCH*HDIM];
__device__ float   g_q   [BATCH*HDIM];
__device__ float   g_sev [BATCH*HDIM];
__device__ float   g_spa [BATCH*HDIM];
__device__ __half2 g_zh  [BATCH*128];
__device__ __half2 g_selfh[BATCH*128];
__device__ __half2 g_hh  [BATCH*128];
__device__ __half2 g_kh  [MROWS*128];
__device__ __half2 g_vh  [MROWS*128];
__device__ __half2 g_xh  [BATCH*XWP];
// Blocked packed weights: per region, word offset of (tile, half, n, kp) =
//   base + ((tile*2 + half)*128 + n)*16 + kp, value = half2(W[2k][col], W[2k+1][col])
// with k = kpOff + tile*16 + kp, col = half*128 + n; zero-padded past kpLen.
#define WB_MU   0        // 18 tiles
#define WB_VAR  73728    // 18
#define WB_SELF 147456   // 2
#define WB_OTH  155648   // 1
#define WB_Q    159744   // 8
#define WB_K    192512   // 8
#define WB_VLO  225280   // 8
#define WB_VHI  258048   // 8
#define WB_ALO  290816   // 8
#define WB_AHI  323584   // 8
#define WB_END  356352
__device__ __half2 g_wp[WB_END];

// ---------------------------------------------------------------------------
// Helpers
// ---------------------------------------------------------------------------
__device__ __forceinline__ uint32_t smem_u32(const void* p) {
    uint32_t a;
    asm("{ .reg .u64 t; cvta.to.shared.u64 t, %1; cvt.u32.u64 %0, t; }"
        : "=r"(a) : "l"(p));
    return a;
}
__device__ __forceinline__ void cpa16(uint32_t dst, const void* src, int bytes) {
    asm volatile("cp.async.cg.shared.global [%0], [%1], 16, %2;"
                 :: "r"(dst), "l"(src), "r"(bytes) : "memory");
}
#define CP_COMMIT() asm volatile("cp.async.commit_group;" ::: "memory")
#define CP_WAIT2()  asm volatile("cp.async.wait_group 2;" ::: "memory")
#define MMA_F16(acc, a, b) \
    asm volatile( \
        "mma.sync.aligned.m16n8k16.row.col.f32.f16.f16.f32 " \
        "{%0,%1,%2,%3},{%4,%5,%6,%7},{%8,%9},{%0,%1,%2,%3};" \
        : "+f"((acc)[0]), "+f"((acc)[1]), "+f"((acc)[2]), "+f"((acc)[3]) \
        : "r"((a)[0]), "r"((a)[1]), "r"((a)[2]), "r"((a)[3]), \
          "r"((b)[0]), "r"((b)[1]))
#define LDSM_X4(r0, r1, r2, r3, addr) \
    asm volatile("ldmatrix.sync.aligned.m8n8.x4.shared.b16 {%0,%1,%2,%3}, [%4];" \
                 : "=r"(r0), "=r"(r1), "=r"(r2), "=r"(r3) : "r"(addr))

// A smem layout (interleaved for ldmatrix): row m, kp-chunk c (16B):
//   p = m>>1, hs = m&1, word = p*prow + ((hs*4 + c) ^ (p&7))*4 + win
// B smem layout (n-major for ldmatrix): row n (64B), chunk c = 2ks+half:
//   byte = n*64 + ((c ^ ((n>>1)&3)) << 4)   -- conflict-free LDSM + STS

// ---------------------------------------------------------------------------
// FP16 mma.sync GEMM, cp.async 4-stage pipeline, ldmatrix A+B fragments.
// C[M,256] = epi(A[M,2*Kp] @ W); W = blocked region (see above).
// BM=128, BN=128, BKp=16, 256 threads (8 warps 2x4), warp tile 64x32.
// EPI : 0 = +bias; 1 = relu(+bias); 2 = relu(+extra[row*256+col]);
//       3 = z-fusion: lv=acc+bias; C = fma(aux, exp(0.5*lv), extra) per elem
// OUTH: 1 = write half2-packed Ch[row*128+col/2]; 0 = write fp32 Cf.
// ---------------------------------------------------------------------------
#define GSMEM_BYTES 65536   // 4 stages x (A 8KB + B 8KB)

template<int EPI, int OUTH>
__global__ void __launch_bounds__(256, 2)
hgemm(const __half2* __restrict__ A, int lda,
      const __half2* __restrict__ W,
      const float* __restrict__ bias,
      const float* __restrict__ extra,
      const float* __restrict__ aux,
      float* __restrict__ Cf, __half2* __restrict__ Ch,
      int Kp)
{
    extern __shared__ char sm[];
    const uint32_t sb = smem_u32(sm);
    const int tid  = threadIdx.x;
    const int lane = tid & 31;
    const int wid  = tid >> 5;
    const int wm   = wid >> 2;
    const int wn   = wid & 3;
    const int g    = lane >> 2;
    const int t    = lane & 3;

    const long rowBase = (long)blockIdx.y * 128;
    const int  colBase = blockIdx.x * 128;
    const int  nHalf   = blockIdx.x;

    // A producer: 2 chunks of 16B; chunk j = (row am, kp-chunk ac)
    int am[2], ac[2]; long abase[2]; uint32_t adst[2];
#pragma unroll
    for (int j = 0; j < 2; j++) {
        int idx = tid + j * 256;     // 0..511
        am[j] = idx >> 2;            // 0..127
        ac[j] = idx & 3;             // 0..3
        abase[j] = (rowBase + am[j]) * (long)lda;
        int p = am[j] >> 1, hs = am[j] & 1;
        adst[j] = (uint32_t)((p * 32 + (((hs * 4) + ac[j]) ^ (p & 7)) * 4) * 4);
    }
    // B producer: 2 chunks; chunk j = (n, c)
    int bn[2], bc[2]; uint32_t bdst[2];
#pragma unroll
    for (int j = 0; j < 2; j++) {
        int idx = tid + j * 256;
        bn[j] = idx >> 2;            // 0..127
        bc[j] = idx & 3;
        bdst[j] = (uint32_t)(bn[j] * 64 + ((bc[j] ^ ((bn[j] >> 1) & 3)) << 4));
    }

    auto issue = [&](int tt, int s) {
        const int ktp = tt << 4;
        const uint32_t sA = sb + (uint32_t)s * 16384u;
        const uint32_t sB = sA + 8192u;
#pragma unroll
        for (int j = 0; j < 2; j++) {
            int kg  = ktp + ac[j] * 4;
            int rem = Kp - kg;
            int bytes = (rem <= 0) ? 0 : ((rem >= 4) ? 16 : rem * 4);
            cpa16(sA + adst[j], A + abase[j] + (bytes ? kg : 0), bytes);
        }
#pragma unroll
        for (int j = 0; j < 2; j++) {
            const __half2* src = W + ((long)(tt * 2 + nHalf) * 128 + bn[j]) * 16 + bc[j] * 4;
            cpa16(sB + bdst[j], src, 16);
        }
    };

    // ldmatrix lane geometry: A fragments
    const int lm = ((lane >> 3) & 1) * 8 + (lane & 7);  // row offset in 16
    const int lc = lane >> 4;                           // chunk offset 0/1
    int apb[4], ahs4[4], ap7[4];
#pragma unroll
    for (int mi = 0; mi < 4; mi++) {
        int m = wm * 64 + mi * 16 + lm;
        apb[mi]  = (m >> 1) * 32;
        ahs4[mi] = (m & 1) * 4;
        ap7[mi]  = (m >> 1) & 7;
    }
    // ldmatrix lane geometry: B fragments (2 x4-calls cover ni 0..3)
    const int bl_m = lane >> 3;          // matrix 0..3
    const int bl_r = lane & 7;
    const int b_half = bl_m & 1;
    int nb64[2], nbx[2];
#pragma unroll
    for (int ci = 0; ci < 2; ci++) {
        int ni = 2 * ci + (bl_m >> 1);
        int n  = wn * 32 + ni * 8 + bl_r;
        nb64[ci] = n * 64;
        nbx[ci]  = (n >> 1) & 3;
    }

    float acc[4][4][4];
#pragma unroll
    for (int mi = 0; mi < 4; mi++)
#pragma unroll
        for (int ni = 0; ni < 4; ni++)
#pragma unroll
            for (int c = 0; c < 4; c++) acc[mi][ni][c] = 0.f;

    const int nt = (Kp + 15) >> 4;
#pragma unroll
    for (int s = 0; s < 3; s++) {
        if (s < nt) issue(s, s);
        CP_COMMIT();
    }

    for (int tt = 0; tt < nt; tt++) {
        CP_WAIT2();
        __syncthreads();
        const int tn = tt + 3;
        if (tn < nt) issue(tn, tn & 3);
        CP_COMMIT();

        const uint32_t sA = sb + (uint32_t)(tt & 3) * 16384u;
        const uint32_t sB = sA + 8192u;
#pragma unroll
        for (int ks = 0; ks < 2; ks++) {
            unsigned a[4][4], b[4][2];
            const int c = 2 * ks + lc;
#pragma unroll
            for (int mi = 0; mi < 4; mi++) {
                uint32_t addr = sA + (uint32_t)((apb[mi] + ((ahs4[mi] + c) ^ ap7[mi]) * 4) * 4);
                LDSM_X4(a[mi][0], a[mi][1], a[mi][2], a[mi][3], addr);
            }
#pragma unroll
            for (int ci = 0; ci < 2; ci++) {
                uint32_t addr = sB + (uint32_t)(nb64[ci] + (((2 * ks + b_half) ^ nbx[ci]) << 4));
                LDSM_X4(b[2 * ci][0], b[2 * ci][1], b[2 * ci + 1][0], b[2 * ci + 1][1], addr);
            }
#pragma unroll
            for (int mi = 0; mi < 4; mi++)
#pragma unroll
                for (int ni = 0; ni < 4; ni++)
                    MMA_F16(acc[mi][ni], a[mi], b[ni]);
        }
    }

#pragma unroll
    for (int mi = 0; mi < 4; mi++) {
#pragma unroll
        for (int d = 0; d < 2; d++) {
            const long row = rowBase + wm * 64 + mi * 16 + g + d * 8;
#pragma unroll
            for (int ni = 0; ni < 4; ni++) {
                const int col = colBase + wn * 32 + ni * 8 + 2 * t;
                float v0 = acc[mi][ni][2 * d];
                float v1 = acc[mi][ni][2 * d + 1];
                if (EPI == 3) {
                    v0 += bias[col]; v1 += bias[col + 1];
                    const float* murow  = extra + row * 256;
                    const float* epsrow = aux + row * 256;
                    v0 = fmaf(epsrow[col],     expf(0.5f * v0), murow[col]);
                    v1 = fmaf(epsrow[col + 1], expf(0.5f * v1), murow[col + 1]);
                } else if (EPI == 2) {
                    v0 += extra[row * 256 + col]; v1 += extra[row * 256 + col + 1];
                    v0 = fmaxf(v0, 0.f); v1 = fmaxf(v1, 0.f);
                } else {
                    v0 += bias[col]; v1 += bias[col + 1];
                    if (EPI == 1) { v0 = fmaxf(v0, 0.f); v1 = fmaxf(v1, 0.f); }
                }
                if (OUTH)
                    Ch[row * 128 + (col >> 1)] = __floats2half2_rn(v0, v1);
                else
                    *reinterpret_cast<float2*>(&Cf[row * 256 + col]) = make_float2(v0, v1);
            }
        }
    }
}

// ---------------------------------------------------------------------------
// Fused oth -> (k, v), fp16 + ldmatrix A&B. Per CTA: 128 agent rows, 512 thr.
// smem words: OTH 16384 (interleaved, prow=256), A1 2048 (prow=32),
//             4 B stages x 2048 (n-major blocked layout).
// ---------------------------------------------------------------------------
#define F_OTH 0
#define F_A1  16384
#define F_STG 18432
#define FSMEM_BYTES 106496

__global__ void __launch_bounds__(512, 2)
fused_okv(const __half2* __restrict__ xh,
          const __half2* __restrict__ WBoth, const float* __restrict__ both,
          const __half2* __restrict__ WBk,   const float* __restrict__ bk_,
          const __half2* __restrict__ WBvlo,
          const float* __restrict__ sev,
          __half2* __restrict__ kb, __half2* __restrict__ vb)
{
    extern __shared__ char sm[];
    unsigned* smw = (unsigned*)sm;
    const uint32_t sb = smem_u32(sm);
    const int tid  = threadIdx.x;
    const int lane = tid & 31;
    const int wid  = tid >> 5;
    const int wm   = wid >> 2;   // 0..3
    const int wn   = wid & 3;    // 0..3
    const int g    = lane >> 2;
    const int t    = lane & 3;
    const long rowBase = (long)blockIdx.x * 128;

    const int lm = ((lane >> 3) & 1) * 8 + (lane & 7);
    const int lc = lane >> 4;
    int apbO[2], apbA[2], ahs4[2], ap7[2];
#pragma unroll
    for (int mi = 0; mi < 2; mi++) {
        int m = wm * 32 + mi * 16 + lm;
        apbO[mi] = (m >> 1) * 256;   // OTH prow = 256 words
        apbA[mi] = (m >> 1) * 32;    // A1 prow = 32 words
        ahs4[mi] = (m & 1) * 4;
        ap7[mi]  = (m >> 1) & 7;
    }
    // B ldmatrix geometry
    const int bl_m = lane >> 3;
    const int bl_r = lane & 7;
    const int b_half = bl_m & 1;
    int nb64[2], nbx[2];
#pragma unroll
    for (int ci = 0; ci < 2; ci++) {
        int ni = 2 * ci + (bl_m >> 1);
        int n  = wn * 32 + ni * 8 + bl_r;
        nb64[ci] = n * 64;
        nbx[ci]  = (n >> 1) & 3;
    }
    // B producer geometry (512 threads = 128n x 4c)
    const int pn = tid >> 2, pc = tid & 3;
    const uint32_t pdst = (uint32_t)(pn * 64 + ((pc ^ ((pn >> 1) & 3)) << 4));

    // ---- A1: agents tile (plain word loads into interleaved layout) ----
    for (int it = tid; it < 2048; it += 512) {
        const int m = it >> 4, w = it & 15;
        unsigned val = 0;
        if (w < 14) {
            long row = rowBase + m;
            int bb = (int)(row / NOTH);
            int nn = (int)(row - (long)bb * NOTH);
            val = *reinterpret_cast<const unsigned*>(&xh[(long)bb * XWP + 18 + nn * 14 + w]);
        }
        const int p = m >> 1, hs = m & 1, c = w >> 2, win = w & 3;
        smw[F_A1 + p * 32 + ((hs * 4 + c) ^ (p & 7)) * 4 + win] = val;
    }
    // ---- W_oth B tiles (2 col-halves, blocked+padded) into stages 0,1 ----
#pragma unroll
    for (int h = 0; h < 2; h++) {
        const __half2* src = WBoth + ((long)h * 128 + pn) * 16 + pc * 4;
        cpa16(sb + (uint32_t)(F_STG + h * 2048) * 4 + pdst, src, 16);
    }
    CP_COMMIT();
    asm volatile("cp.async.wait_group 0;" ::: "memory");
    __syncthreads();

    // ---- stage 1: oth = relu(agents @ W_oth + b) -> OTH (half2, interleaved) ----
    for (int h = 0; h < 2; h++) {
        float acc[2][4][4];
#pragma unroll
        for (int mi = 0; mi < 2; mi++)
#pragma unroll
            for (int ni = 0; ni < 4; ni++)
#pragma unroll
                for (int c = 0; c < 4; c++) acc[mi][ni][c] = 0.f;
        const uint32_t sB = sb + (uint32_t)(F_STG + h * 2048) * 4;
#pragma unroll
        for (int ks = 0; ks < 2; ks++) {
            unsigned a[2][4], b[4][2];
            const int c = 2 * ks + lc;
#pragma unroll
            for (int mi = 0; mi < 2; mi++) {
                uint32_t addr = sb + (uint32_t)((F_A1 + apbA[mi] + ((ahs4[mi] + c) ^ ap7[mi]) * 4) * 4);
                LDSM_X4(a[mi][0], a[mi][1], a[mi][2], a[mi][3], addr);
            }
#pragma unroll
            for (int ci = 0; ci < 2; ci++) {
                uint32_t addr = sB + (uint32_t)(nb64[ci] + (((2 * ks + b_half) ^ nbx[ci]) << 4));
                LDSM_X4(b[2 * ci][0], b[2 * ci][1], b[2 * ci + 1][0], b[2 * ci + 1][1], addr);
            }
#pragma unroll
            for (int mi = 0; mi < 2; mi++)
#pragma unroll
                for (int ni = 0; ni < 4; ni++)
                    MMA_F16(acc[mi][ni], a[mi], b[ni]);
        }
        // epilogue -> OTH (interleaved: chunk c = h*4 + wn lines, win = t)
#pragma unroll
        for (int mi = 0; mi < 2; mi++)
#pragma unroll
            for (int d = 0; d < 2; d++) {
                const int rm = wm * 32 + mi * 16 + g + d * 8;
                const int p = rm >> 1, hs = rm & 1;
#pragma unroll
                for (int ni = 0; ni < 4; ni++) {
                    const int col = h * 128 + wn * 32 + ni * 8 + 2 * t;
                    float v0 = fmaxf(acc[mi][ni][2 * d]     + both[col],     0.f);
                    float v1 = fmaxf(acc[mi][ni][2 * d + 1] + both[col + 1], 0.f);
                    __half2 hv = __floats2half2_rn(v0, v1);
                    const int line = h * 4 + wn;             // c>>2
                    smw[F_OTH + p * 256 + line * 32 + ((hs * 4 + ni) ^ (p & 7)) * 4 + t] =
                        *reinterpret_cast<unsigned*>(&hv);
                }
            }
    }
    __syncthreads();

    // ---- stage 2: 4 chunks {k-lo, k-hi, v-lo, v-hi}, Kp=128, 8 tiles, 4-stage ----
    for (int cc = 0; cc < 4; cc++) {
        const __half2* W = (cc < 2) ? WBk : WBvlo;
        const int nh = cc & 1;
        __half2* Co = (cc < 2) ? kb : vb;
        const int colOff = nh * 128;

        auto issueB = [&](int tt, int s) {
            const __half2* src = W + ((long)(tt * 2 + nh) * 128 + pn) * 16 + pc * 4;
            cpa16(sb + (uint32_t)(F_STG + s * 2048) * 4 + pdst, src, 16);
        };

        float acc[2][4][4];
#pragma unroll
        for (int mi = 0; mi < 2; mi++)
#pragma unroll
            for (int ni = 0; ni < 4; ni++)
#pragma unroll
                for (int c = 0; c < 4; c++) acc[mi][ni][c] = 0.f;

#pragma unroll
        for (int s = 0; s < 3; s++) {
            issueB(s, s);
            CP_COMMIT();
        }

        for (int tt = 0; tt < 8; tt++) {
            CP_WAIT2();
            __syncthreads();
            if (tt + 3 < 8) issueB(tt + 3, (tt + 3) & 3);
            CP_COMMIT();

            const uint32_t sB = sb + (uint32_t)(F_STG + (tt & 3) * 2048) * 4;
#pragma unroll
            for (int ks = 0; ks < 2; ks++) {
                unsigned a[2][4], b[4][2];
                const int c3 = 2 * ks + lc;
#pragma unroll
                for (int mi = 0; mi < 2; mi++) {
                    uint32_t addr = sb + (uint32_t)((F_OTH + apbO[mi] + tt * 32
                                     + ((ahs4[mi] + c3) ^ ap7[mi]) * 4) * 4);
                    LDSM_X4(a[mi][0], a[mi][1], a[mi][2], a[mi][3], addr);
                }
#pragma unroll
                for (int ci = 0; ci < 2; ci++) {
                    uint32_t addr = sB + (uint32_t)(nb64[ci] + (((2 * ks + b_half) ^ nbx[ci]) << 4));
                    LDSM_X4(b[2 * ci][0], b[2 * ci][1], b[2 * ci + 1][0], b[2 * ci + 1][1], addr);
                }
#pragma unroll
                for (int mi = 0; mi < 2; mi++)
#pragma unroll
                    for (int ni = 0; ni < 4; ni++)
                        MMA_F16(acc[mi][ni], a[mi], b[ni]);
            }
        }

#pragma unroll
        for (int mi = 0; mi < 2; mi++)
#pragma unroll
            for (int d = 0; d < 2; d++) {
                const long row = rowBase + wm * 32 + mi * 16 + g + d * 8;
                const float* sv = (cc >= 2) ? (sev + (row / NOTH) * 256) : nullptr;
#pragma unroll
                for (int ni = 0; ni < 4; ni++) {
                    const int col = colOff + wn * 32 + ni * 8 + 2 * t;
                    float v0 = acc[mi][ni][2 * d];
                    float v1 = acc[mi][ni][2 * d + 1];
                    if (cc < 2) { v0 += bk_[col]; v1 += bk_[col + 1]; }
                    else        { v0 += sv[col];  v1 += sv[col + 1]; }
                    v0 = fmaxf(v0, 0.f); v1 = fmaxf(v1, 0.f);
                    Co[row * 128 + (col >> 1)] = __floats2half2_rn(v0, v1);
                }
            }
    }
}

// ---------------------------------------------------------------------------
// Packing kernels
// ---------------------------------------------------------------------------
__global__ void packWB(const float* __restrict__ Wmu, const float* __restrict__ Wvar,
                       const float* __restrict__ Wself, const float* __restrict__ Woth,
                       const float* __restrict__ Wq, const float* __restrict__ Wk,
                       const float* __restrict__ Wv, const float* __restrict__ Wa,
                       __half2* __restrict__ out)
{
    int i = blockIdx.x * blockDim.x + threadIdx.x;
    if (i >= WB_END) return;
    const float* src; int base, kpOff, kpLen;
    if      (i < WB_VAR)  { src = Wmu;   base = WB_MU;   kpOff = 0;   kpLen = 284; }
    else if (i < WB_SELF) { src = Wvar;  base = WB_VAR;  kpOff = 0;   kpLen = 284; }
    else if (i < WB_OTH)  { src = Wself; base = WB_SELF; kpOff = 0;   kpLen = 18;  }
    else if (i < WB_Q)    { src = Woth;  base = WB_OTH;  kpOff = 0;   kpLen = 14;  }
    else if (i < WB_K)    { src = Wq;    base = WB_Q;    kpOff = 0;   kpLen = 128; }
    else if (i < WB_VLO)  { src = Wk;    base = WB_K;    kpOff = 0;   kpLen = 128; }
    else if (i < WB_VHI)  { src = Wv;    base = WB_VLO;  kpOff = 0;   kpLen = 128; }
    else if (i < WB_ALO)  { src = Wv;    base = WB_VHI;  kpOff = 128; kpLen = 128; }
    else if (i < WB_AHI)  { src = Wa;    base = WB_ALO;  kpOff = 0;   kpLen = 128; }
    else                  { src = Wa;    base = WB_AHI;  kpOff = 128; kpLen = 128; }
    int r    = i - base;
    int tile = r >> 12;
    int rem  = r & 4095;
    int half = rem >> 11;
    int n    = (rem >> 4) & 127;
    int kp   = rem & 15;
    int kpl  = tile * 16 + kp;
    __half2 v = __floats2half2_rn(0.f, 0.f);
    if (kpl < kpLen) {
        int k   = kpOff + kpl;
        int col = half * 128 + n;
        v = __floats2half2_rn(src[(2 * k) * 256 + col], src[(2 * k + 1) * 256 + col]);
    }
    out[i] = v;
}
__global__ void packX(const float2* __restrict__ in, __half2* __restrict__ out, int n)
{
    int i = blockIdx.x * blockDim.x + threadIdx.x;
    if (i < n) {
        float2 f = in[i];
        out[i] = __floats2half2_rn(f.x, f.y);
    }
}

// ---------------------------------------------------------------------------
// Attention: scores = q.k/16 -> softmax(19) -> h = att @ v (half2 I/O)
// ---------------------------------------------------------------------------
__global__ void __launch_bounds__(256)
att_kernel(const float* __restrict__ q,
           const __half2* __restrict__ k2,
           const __half2* __restrict__ v2,
           __half2* __restrict__ h2,
           float* __restrict__ att_out)
{
    const int b   = blockIdx.x;
    const int tid = threadIdx.x;
    const int wid = tid >> 5;
    const int lane = tid & 31;

    __shared__ float qs[HDIM];
    __shared__ float sc[32];

    qs[tid] = q[(long)b * HDIM + tid];
    __syncthreads();

    for (int n = wid; n < NOTH; n += 8) {
        const __half2* kp = k2 + ((long)b * NOTH + n) * 128;
        float p = 0.f;
#pragma unroll
        for (int j = 0; j < 4; j++) {
            const int w = lane + 32 * j;
            float2 f = __half22float2(kp[w]);
            p = fmaf(qs[2 * w], f.x, p);
            p = fmaf(qs[2 * w + 1], f.y, p);
        }
#pragma unroll
        for (int off = 16; off > 0; off >>= 1)
            p += __shfl_xor_sync(0xffffffffu, p, off);
        if (lane == 0) sc[n] = p * 0.0625f;
    }
    __syncthreads();

    if (wid == 0) {
        float s = (lane < NOTH) ? sc[lane] : -INFINITY;
        float m = s;
#pragma unroll
        for (int off = 16; off > 0; off >>= 1)
            m = fmaxf(m, __shfl_xor_sync(0xffffffffu, m, off));
        float e = (lane < NOTH) ? expf(s - m) : 0.f;
        float sum = e;
#pragma unroll
        for (int off = 16; off > 0; off >>= 1)
            sum += __shfl_xor_sync(0xffffffffu, sum, off);
        const float a = e / sum;
        if (lane < NOTH) {
            sc[lane] = a;
            att_out[(long)b * NOTH + lane] = a;
        }
    }
    __syncthreads();

    if (tid < 128) {
        const __half2* vp = v2 + (long)b * NOTH * 128 + tid;
        float ax = 0.f, ay = 0.f;
#pragma unroll
        for (int n = 0; n < NOTH; n++) {
            float2 f = __half22float2(vp[(long)n * 128]);
            ax = fmaf(sc[n], f.x, ax);
            ay = fmaf(sc[n], f.y, ay);
        }
        h2[(long)b * 128 + tid] = __floats2half2_rn(ax, ay);
    }
}

// ---------------------------------------------------------------------------
// Launch
// ---------------------------------------------------------------------------
extern "C" void kernel_launch(void* const* d_in, const int* in_sizes, int n_in,
                              void* d_out, int out_size)
{
    const float* x      = (const float*)d_in[0];
    const float* eps    = (const float*)d_in[1];
    const float* W_mu   = (const float*)d_in[2];
    const float* b_mu   = (const float*)d_in[3];
    const float* W_var  = (const float*)d_in[4];
    const float* b_var  = (const float*)d_in[5];
    const float* W_self = (const float*)d_in[6];
    const float* b_self = (const float*)d_in[7];
    const float* W_oth  = (const float*)d_in[8];
    const float* b_oth  = (const float*)d_in[9];
    const float* W_q    = (const float*)d_in[10];
    const float* b_q    = (const float*)d_in[11];
    const float* W_k    = (const float*)d_in[12];
    const float* b_k    = (const float*)d_in[13];
    const float* W_v    = (const float*)d_in[14];
    const float* b_v    = (const float*)d_in[15];
    const float* W_a    = (const float*)d_in[16];
    const float* b_a    = (const float*)d_in[17];

    float* out_main = (float*)d_out;
    float* out_att  = (float*)d_out + (long)BATCH * HDIM;

    float *mu, *q, *sev, *spa;
    __half2 *zh, *selfh, *hh, *kh, *vh, *xh, *wp;
    cudaGetSymbolAddress((void**)&mu,    g_mu);
    cudaGetSymbolAddress((void**)&q,     g_q);
    cudaGetSymbolAddress((void**)&sev,   g_sev);
    cudaGetSymbolAddress((void**)&spa,   g_spa);
    cudaGetSymbolAddress((void**)&zh,    g_zh);
    cudaGetSymbolAddress((void**)&selfh, g_selfh);
    cudaGetSymbolAddress((void**)&hh,    g_hh);
    cudaGetSymbolAddress((void**)&kh,    g_kh);
    cudaGetSymbolAddress((void**)&vh,    g_vh);
    cudaGetSymbolAddress((void**)&xh,    g_xh);
    cudaGetSymbolAddress((void**)&wp,    g_wp);

    cudaFuncSetAttribute(hgemm<0,0>, cudaFuncAttributeMaxDynamicSharedMemorySize, GSMEM_BYTES);
    cudaFuncSetAttribute(hgemm<1,0>, cudaFuncAttributeMaxDynamicSharedMemorySize, GSMEM_BYTES);
    cudaFuncSetAttribute(hgemm<1,1>, cudaFuncAttributeMaxDynamicSharedMemorySize, GSMEM_BYTES);
    cudaFuncSetAttribute(hgemm<2,0>, cudaFuncAttributeMaxDynamicSharedMemorySize, GSMEM_BYTES);
    cudaFuncSetAttribute(hgemm<3,1>, cudaFuncAttributeMaxDynamicSharedMemorySize, GSMEM_BYTES);
    cudaFuncSetAttribute(fused_okv,  cudaFuncAttributeMaxDynamicSharedMemorySize, FSMEM_BYTES);

    // Pack operands (blocked weights + half2 x)
    packWB<<<(WB_END + 255) / 256, 256>>>(W_mu, W_var, W_self, W_oth,
                                          W_q, W_k, W_v, W_a, wp);
    {
        int nx = BATCH * XWP;
        packX<<<(nx + 255) / 256, 256>>>((const float2*)x, xh, nx);
    }

    const dim3 blk(256);
    const dim3 gB(2, BATCH / 128);

    // mu = x @ W_mu + b_mu (fp32 out)
    hgemm<0,0><<<gB, blk, GSMEM_BYTES>>>(xh, XWP, wp + WB_MU, b_mu, nullptr, nullptr, mu, nullptr, 284);
    // z = eps * exp(0.5*(x@W_var+b_var)) + mu  (half out)
    hgemm<3,1><<<gB, blk, GSMEM_BYTES>>>(xh, XWP, wp + WB_VAR, b_var, mu, eps, nullptr, zh, 284);
    // self_em = relu(x[:, :36] @ W_self + b) (half out)
    hgemm<1,1><<<gB, blk, GSMEM_BYTES>>>(xh, XWP, wp + WB_SELF, b_self, nullptr, nullptr, nullptr, selfh, 18);
    // sev = self_em @ W_v[256:] + b_v (fp32 out)
    hgemm<0,0><<<gB, blk, GSMEM_BYTES>>>(selfh, 128, wp + WB_VHI, b_v, nullptr, nullptr, sev, nullptr, 128);
    // fused: oth (smem) -> k, v (half out)
    fused_okv<<<MROWS / 128, 512, FSMEM_BYTES>>>(xh, wp + WB_OTH, b_oth,
                                                 wp + WB_K, b_k, wp + WB_VLO,
                                                 sev, kh, vh);
    // q = relu(z @ W_q + b) (fp32 out; feeds att only)
    hgemm<1,0><<<gB, blk, GSMEM_BYTES>>>(zh, 128, wp + WB_Q, b_q, nullptr, nullptr, q, nullptr, 128);
    // attention
    att_kernel<<<BATCH, 256>>>(q, kh, vh, hh, out_att);
    // spa = self_em @ W_a[256:] + b_a (fp32 out)
    hgemm<0,0><<<gB, blk, GSMEM_BYTES>>>(selfh, 128, wp + WB_AHI, b_a, nullptr, nullptr, spa, nullptr, 128);
    // out = relu(h @ W_a[:256] + spa) (fp32 out)
    hgemm<2,0><<<gB, blk, GSMEM_BYTES>>>(hh, 128, wp + WB_ALO, nullptr, spa, nullptr, out_main, nullptr, 128);
}